// round 7
// baseline (speedup 1.0000x reference)
#include <cuda_runtime.h>
#include <math.h>

// ---------------- problem constants ----------------
#define NN 10000
#define DD 256
#define EE 320000
#define MAXNORM 0.996f          // (1 - 4e-3)/sqrt(c), c=1
#define MINNORM 1e-15f
#define ATANH_CLIP (1.0f - 1e-7f)

// ---------------- scratch (static device globals; no allocation) ----------
__device__ float g_h  [NN * DD];
__device__ float g_xt [NN * DD];
__device__ float g_bias[DD];
__device__ float g_biasy2;
// CSR-by-dst
__device__ int   g_cnt[NN];
__device__ int   g_off[NN + 1];
__device__ int   g_pos[NN];
__device__ int   g_csr_src[EE];
__device__ float g_csr_w[EE];

// ---------------- numerics (flag-independent accurate tanh/atanh) ---------
__device__ __forceinline__ float tanh_acc(float x) {
    float a = fabsf(x);
    if (a > 15.f) return copysignf(1.f, x);
    float s = expm1f(2.f * a);
    float r = s / (s + 2.f);
    return copysignf(r, x);
}
__device__ __forceinline__ float atanh_clip(float r) {
    float a = fminf(r, ATANH_CLIP);
    return 0.5f * log1pf(2.f * a / (1.f - a));
}

// ---------------- small float4 helpers ----------------
__device__ __forceinline__ float d4(float4 v)  { return v.x*v.x + v.y*v.y + v.z*v.z + v.w*v.w; }
__device__ __forceinline__ float dd4(float4 a, float4 b) { return a.x*b.x + a.y*b.y + a.z*b.z + a.w*b.w; }
__device__ __forceinline__ float4 s4(float4 v, float s) { return make_float4(v.x*s, v.y*s, v.z*s, v.w*s); }
__device__ __forceinline__ void fma4(float4& a, float4 v, float w) {
    a.x = fmaf(v.x, w, a.x); a.y = fmaf(v.y, w, a.y);
    a.z = fmaf(v.z, w, a.z); a.w = fmaf(v.w, w, a.w);
}

// ---------------- packed f32x2 (sm_103a FFMA2) ----------------
typedef unsigned long long u64t;
union F4U2 { float4 f; u64t u[2]; };
__device__ __forceinline__ void ffma2(u64t& d, u64t a, u64t b) {
    asm("fma.rn.f32x2 %0, %1, %2, %0;" : "+l"(d) : "l"(a), "l"(b));
}
__device__ __forceinline__ u64t pack2(float v) {
    u64t r;
    asm("mov.b64 %0, {%1, %1};" : "=l"(r) : "f"(v));
    return r;
}

__device__ __forceinline__ float wredsum(float v) {
    #pragma unroll
    for (int o = 16; o; o >>= 1) v += __shfl_xor_sync(0xffffffffu, v, o);
    return v;
}
__device__ __forceinline__ float rownorm(float4 a0, float4 a1) {
    return fmaxf(sqrtf(wredsum(d4(a0) + d4(a1))), MINNORM);
}

// ---------------- stage A: h = proj(expmap0(x)); also zero g_cnt ---------
__global__ void k_init(const float* __restrict__ x) {
    int gi = blockIdx.x * blockDim.x + threadIdx.x;
    if (gi < NN) g_cnt[gi] = 0;
    int w = threadIdx.x >> 5, lane = threadIdx.x & 31;
    int row = blockIdx.x * 8 + w;
    if (row >= NN) return;
    const float4* xp = (const float4*)x + (size_t)row * 64;
    float4 v0 = xp[lane], v1 = xp[lane + 32];
    float n = rownorm(v0, v1);
    float s = tanh_acc(n) / n;
    float4 e0 = s4(v0, s), e1 = s4(v1, s);
    float n2 = rownorm(e0, e1);
    if (n2 > MAXNORM) { float f = MAXNORM / n2; e0 = s4(e0, f); e1 = s4(e1, f); }
    float4* hp = (float4*)g_h + (size_t)row * 64;
    hp[lane] = e0; hp[lane + 32] = e1;
}

// ---------------- CSR build ----------------
__global__ void k_hist(const int* __restrict__ edst) {
    int i = blockIdx.x * blockDim.x + threadIdx.x;
    if (i < EE) atomicAdd(&g_cnt[edst[i]], 1);
}

__global__ __launch_bounds__(1024) void k_scan() {
    __shared__ int warp_sums[32];
    int tid = threadIdx.x, lane = tid & 31, wid = tid >> 5;
    int base = tid * 10;
    int v[10]; int s = 0;
    #pragma unroll
    for (int j = 0; j < 10; j++) {
        int i = base + j;
        v[j] = (i < NN) ? g_cnt[i] : 0;
        s += v[j];
    }
    int x = s;
    #pragma unroll
    for (int o = 1; o < 32; o <<= 1) {
        int y = __shfl_up_sync(0xffffffffu, x, o);
        if (lane >= o) x += y;
    }
    if (lane == 31) warp_sums[wid] = x;
    __syncthreads();
    if (wid == 0) {
        int t = warp_sums[lane];
        #pragma unroll
        for (int o = 1; o < 32; o <<= 1) {
            int y = __shfl_up_sync(0xffffffffu, t, o);
            if (lane >= o) t += y;
        }
        warp_sums[lane] = t;
    }
    __syncthreads();
    int prefix = ((wid > 0) ? warp_sums[wid - 1] : 0) + (x - s);  // exclusive
    #pragma unroll
    for (int j = 0; j < 10; j++) {
        int i = base + j;
        if (i < NN) { g_off[i] = prefix; g_pos[i] = prefix; }
        prefix += v[j];
    }
    if (tid == 1023) g_off[NN] = prefix;
}

__global__ void k_fill(const int* __restrict__ esrc, const int* __restrict__ edst,
                       const float* __restrict__ ew) {
    int i = blockIdx.x * blockDim.x + threadIdx.x;
    if (i < EE) {
        int d = edst[i];
        int p = atomicAdd(&g_pos[d], 1);
        g_csr_src[p] = esrc[i];
        g_csr_w[p]   = ew[i];
    }
}

// ---------------- bias: hyp_bias = proj(expmap0(b)), plus |bias|^2 --------
__global__ void k_bias(const float* __restrict__ b) {
    int lane = threadIdx.x;   // 32 threads, 1 warp
    const float4* bp = (const float4*)b;
    float4 v0 = bp[lane], v1 = bp[lane + 32];
    float n = rownorm(v0, v1);
    float s = tanh_acc(n) / n;
    v0 = s4(v0, s); v1 = s4(v1, s);
    float n2 = rownorm(v0, v1);
    if (n2 > MAXNORM) { float f = MAXNORM / n2; v0 = s4(v0, f); v1 = s4(v1, f); }
    float y2 = wredsum(d4(v0) + d4(v1));
    ((float4*)g_bias)[lane] = v0;
    ((float4*)g_bias)[lane + 32] = v1;
    if (lane == 0) g_biasy2 = y2;
}

// ---------------- fused GEMM + HypLinear tail + logmap0 → g_xt ------------
// tile: 40 rows x 256 cols. Warp ty owns rows m0+ty*5..+4 completely.
// Packed-f32x2 mainloop: each accumulator u64 = 2 adjacent output columns.
#define TM 40
__global__ __launch_bounds__(256, 2) void k_gemmpre(const float* __restrict__ Wm) {
    __shared__ float As[TM][36];      // [m][k], pad 36
    __shared__ float Bs[32][256];     // [k][j]
    int tid = threadIdx.x;
    int tx = tid & 31, ty = tid >> 5;
    int m0 = blockIdx.x * TM;

    // acc[r][p]: row r, pair p. p=0,1 -> cols tx*4..+3 ; p=2,3 -> cols 128+tx*4..+3
    u64t acc[5][4];
    #pragma unroll
    for (int r = 0; r < 5; r++)
        #pragma unroll
        for (int p = 0; p < 4; p++) acc[r][p] = 0ull;

    for (int k0 = 0; k0 < 256; k0 += 32) {
        // load A tile: 40x32 floats = 320 float4
        {
            int idx = tid;
            if (idx < 320) {
                int r = idx >> 3, c4 = idx & 7;
                float4 a = *(const float4*)(g_h + (size_t)(m0 + r) * 256 + k0 + c4 * 4);
                As[r][c4*4+0] = a.x; As[r][c4*4+1] = a.y; As[r][c4*4+2] = a.z; As[r][c4*4+3] = a.w;
            }
            idx = tid + 256;
            if (idx < 320) {
                int r = idx >> 3, c4 = idx & 7;
                float4 a = *(const float4*)(g_h + (size_t)(m0 + r) * 256 + k0 + c4 * 4);
                As[r][c4*4+0] = a.x; As[r][c4*4+1] = a.y; As[r][c4*4+2] = a.z; As[r][c4*4+3] = a.w;
            }
        }
        // load B tile: thread j=tid loads W[j][k0..k0+31], stores Bs[k][j]
        {
            const float4* wr = (const float4*)(Wm + (size_t)tid * 256 + k0);
            #pragma unroll
            for (int c4 = 0; c4 < 8; c4++) {
                float4 b = __ldg(&wr[c4]);
                Bs[c4*4+0][tid] = b.x; Bs[c4*4+1][tid] = b.y;
                Bs[c4*4+2][tid] = b.z; Bs[c4*4+3][tid] = b.w;
            }
        }
        __syncthreads();
        #pragma unroll
        for (int kk4 = 0; kk4 < 8; kk4++) {
            float4 ar[5];
            #pragma unroll
            for (int r = 0; r < 5; r++)
                ar[r] = *(const float4*)&As[ty*5 + r][kk4*4];
            #pragma unroll
            for (int q = 0; q < 4; q++) {
                int kk = kk4*4 + q;
                F4U2 b0, b1;
                b0.f = *(const float4*)&Bs[kk][tx*4];
                b1.f = *(const float4*)&Bs[kk][128 + tx*4];
                #pragma unroll
                for (int r = 0; r < 5; r++) {
                    float av = (q == 0) ? ar[r].x : (q == 1) ? ar[r].y : (q == 2) ? ar[r].z : ar[r].w;
                    u64t av2 = pack2(av);
                    ffma2(acc[r][0], av2, b0.u[0]);
                    ffma2(acc[r][1], av2, b0.u[1]);
                    ffma2(acc[r][2], av2, b1.u[0]);
                    ffma2(acc[r][3], av2, b1.u[1]);
                }
            }
        }
        __syncthreads();
    }

    // ---- fused epilogue: per warp, 5 complete rows ----
    float4 bb0 = ((const float4*)g_bias)[tx];
    float4 bb1 = ((const float4*)g_bias)[32 + tx];
    float y2 = g_biasy2;
    #pragma unroll
    for (int r = 0; r < 5; r++) {
        int m = m0 + ty * 5 + r;
        F4U2 lo, hi;
        lo.u[0] = acc[r][0]; lo.u[1] = acc[r][1];
        hi.u[0] = acc[r][2]; hi.u[1] = acc[r][3];
        float4 mv0 = lo.f, mv1 = hi.f;

        // h row reload for xn
        const float4* hp = (const float4*)(g_h + (size_t)m * 256);
        float4 h0 = hp[tx], h1 = hp[32 + tx];
        float xn = rownorm(h0, h1);

        // mobius_matvec scaling
        float mn2 = wredsum(d4(mv0) + d4(mv1));
        bool zero = (mn2 == 0.f);
        float mxn = fmaxf(sqrtf(mn2), MINNORM);
        float arg = mxn / xn * atanh_clip(xn);
        float sc = tanh_acc(arg) / mxn;
        if (zero) sc = 0.f;
        float4 r0 = s4(mv0, sc), r1 = s4(mv1, sc);
        float rn = rownorm(r0, r1);
        if (rn > MAXNORM) { float f = MAXNORM / rn; r0 = s4(r0, f); r1 = s4(r1, f); }

        // mobius_add with hyp_bias
        float x2 = wredsum(d4(r0) + d4(r1));
        float xy = wredsum(dd4(r0, bb0) + dd4(r1, bb1));
        float ca = 1.f + 2.f * xy + y2;
        float cb = 1.f - x2;
        float den = fmaxf(1.f + 2.f * xy + x2 * y2, MINNORM);
        float4 q0, q1;
        q0.x = (ca*r0.x + cb*bb0.x)/den; q0.y = (ca*r0.y + cb*bb0.y)/den;
        q0.z = (ca*r0.z + cb*bb0.z)/den; q0.w = (ca*r0.w + cb*bb0.w)/den;
        q1.x = (ca*r1.x + cb*bb1.x)/den; q1.y = (ca*r1.y + cb*bb1.y)/den;
        q1.z = (ca*r1.z + cb*bb1.z)/den; q1.w = (ca*r1.w + cb*bb1.w)/den;
        float qn = rownorm(q0, q1);
        if (qn > MAXNORM) { float f = MAXNORM / qn; q0 = s4(q0, f); q1 = s4(q1, f); }

        // logmap0
        float pn = rownorm(q0, q1);
        float ls = atanh_clip(pn) / pn;
        q0 = s4(q0, ls); q1 = s4(q1, ls);

        float4* xp = (float4*)(g_xt + (size_t)m * 256);
        xp[tx] = q0; xp[32 + tx] = q1;
    }
}

// ---------------- fused CSR aggregation + HypAgg/HypAct tail -------------
__global__ __launch_bounds__(256) void k_aggpost(float* __restrict__ out, int write_out) {
    int w = threadIdx.x >> 5, lane = threadIdx.x & 31;
    int row = blockIdx.x * 8 + w;
    if (row >= NN) return;
    int beg = g_off[row], end = g_off[row + 1];

    float4 a0 = make_float4(0.f, 0.f, 0.f, 0.f);
    float4 a1 = make_float4(0.f, 0.f, 0.f, 0.f);

    for (int c = beg; c < end; c += 32) {
        int n = end - c; if (n > 32) n = 32;
        int   sv = 0; float wv = 0.f;
        if (lane < n) {
            sv = __ldg(&g_csr_src[c + lane]);
            wv = __ldg(&g_csr_w[c + lane]);
        }
        int j = 0;
        for (; j + 1 < n; j += 2) {
            int   s0 = __shfl_sync(0xffffffffu, sv, j);
            int   s1 = __shfl_sync(0xffffffffu, sv, j + 1);
            float w0 = __shfl_sync(0xffffffffu, wv, j);
            float w1 = __shfl_sync(0xffffffffu, wv, j + 1);
            const float4* p0 = (const float4*)g_xt + (size_t)s0 * 64;
            const float4* p1 = (const float4*)g_xt + (size_t)s1 * 64;
            float4 u0 = __ldg(&p0[lane]);
            float4 u1 = __ldg(&p0[lane + 32]);
            float4 t0 = __ldg(&p1[lane]);
            float4 t1 = __ldg(&p1[lane + 32]);
            fma4(a0, u0, w0); fma4(a1, u1, w0);
            fma4(a0, t0, w1); fma4(a1, t1, w1);
        }
        if (j < n) {
            int   s0 = __shfl_sync(0xffffffffu, sv, j);
            float w0 = __shfl_sync(0xffffffffu, wv, j);
            const float4* p0 = (const float4*)g_xt + (size_t)s0 * 64;
            float4 u0 = __ldg(&p0[lane]);
            float4 u1 = __ldg(&p0[lane + 32]);
            fma4(a0, u0, w0); fma4(a1, u1, w0);
        }
    }

    // expmap0
    float n1 = rownorm(a0, a1);
    float s = tanh_acc(n1) / n1;
    float4 e0 = s4(a0, s), e1 = s4(a1, s);
    // proj
    float n2 = rownorm(e0, e1);
    if (n2 > MAXNORM) { float f = MAXNORM / n2; e0 = s4(e0, f); e1 = s4(e1, f); }
    // logmap0 + relu
    float pn = rownorm(e0, e1);
    float ls = atanh_clip(pn) / pn;
    float4 u0, u1;
    u0.x = fmaxf(e0.x * ls, 0.f); u0.y = fmaxf(e0.y * ls, 0.f);
    u0.z = fmaxf(e0.z * ls, 0.f); u0.w = fmaxf(e0.w * ls, 0.f);
    u1.x = fmaxf(e1.x * ls, 0.f); u1.y = fmaxf(e1.y * ls, 0.f);
    u1.z = fmaxf(e1.z * ls, 0.f); u1.w = fmaxf(e1.w * ls, 0.f);
    // expmap0
    float un = rownorm(u0, u1);
    float s2 = tanh_acc(un) / un;
    float4 o0 = s4(u0, s2), o1 = s4(u1, s2);
    // proj
    float n3 = rownorm(o0, o1);
    if (n3 > MAXNORM) { float f = MAXNORM / n3; o0 = s4(o0, f); o1 = s4(o1, f); }

    float4* dst = write_out ? ((float4*)out + (size_t)row * 64)
                            : ((float4*)g_h + (size_t)row * 64);
    dst[lane] = o0; dst[lane + 32] = o1;
}

// ---------------- launch ----------------
extern "C" void kernel_launch(void* const* d_in, const int* in_sizes, int n_in,
                              void* d_out, int out_size) {
    const float* x    = (const float*)d_in[0];
    const float* W1   = (const float*)d_in[1];
    const float* b1   = (const float*)d_in[2];
    const float* W2   = (const float*)d_in[3];
    const float* b2   = (const float*)d_in[4];
    const float* ew   = (const float*)d_in[5];
    const int*   esrc = (const int*)d_in[6];
    const int*   edst = (const int*)d_in[7];
    float* out = (float*)d_out;
    (void)in_sizes; (void)n_in; (void)out_size;

    const int rowBlocks = (NN + 7) / 8;
    const int gemmBlocks = NN / TM;               // 250, exact
    const int eBlocks = (EE + 255) / 256;

    k_init<<<rowBlocks, 256>>>(x);

    // CSR build (once; reused by both layers)
    k_hist<<<eBlocks, 256>>>(edst);
    k_scan<<<1, 1024>>>();
    k_fill<<<eBlocks, 256>>>(esrc, edst, ew);

    // layer 1
    k_bias<<<1, 32>>>(b1);
    k_gemmpre<<<gemmBlocks, 256>>>(W1);
    k_aggpost<<<rowBlocks, 256>>>(out, 0);

    // layer 2
    k_bias<<<1, 32>>>(b2);
    k_gemmpre<<<gemmBlocks, 256>>>(W2);
    k_aggpost<<<rowBlocks, 256>>>(out, 1);
}

// round 12
// speedup vs baseline: 1.3236x; 1.3236x over previous
#include <cuda_runtime.h>
#include <cuda_bf16.h>
#include <math.h>
#include <stdint.h>

// ---------------- problem constants ----------------
#define NN 10000
#define DD 256
#define EE 320000
#define MAXNORM 0.996f
#define MINNORM 1e-15f
#define ATANH_CLIP (1.0f - 1e-7f)

#define GB 79
#define NNP (GB * 128)    // 10112 padded rows

// ---------------- scratch ----------------
__device__ float g_h  [NN * DD];
__device__ float g_mx [NN * DD];
__device__ float g_xt [NN * DD];
__device__ float g_bias[DD];
__device__ float g_biasy2;
__device__ __nv_bfloat16 g_ah[NNP * DD];
__device__ __nv_bfloat16 g_al[NNP * DD];
__device__ __nv_bfloat16 g_wh[2 * DD * DD];
__device__ __nv_bfloat16 g_wl[2 * DD * DD];
// CSR-by-dst
__device__ int   g_cnt[NN];
__device__ int   g_off[NN + 1];
__device__ int   g_pos[NN];
__device__ int   g_csr_src[EE];
__device__ float g_csr_w[EE];

// ---------------- numerics ----------------
__device__ __forceinline__ float tanh_acc(float x) {
    float a = fabsf(x);
    if (a > 15.f) return copysignf(1.f, x);
    float s = expm1f(2.f * a);
    float r = s / (s + 2.f);
    return copysignf(r, x);
}
__device__ __forceinline__ float atanh_clip(float r) {
    float a = fminf(r, ATANH_CLIP);
    return 0.5f * log1pf(2.f * a / (1.f - a));
}

// ---------------- helpers ----------------
__device__ __forceinline__ float d4(float4 v)  { return v.x*v.x + v.y*v.y + v.z*v.z + v.w*v.w; }
__device__ __forceinline__ float dd4(float4 a, float4 b) { return a.x*b.x + a.y*b.y + a.z*b.z + a.w*b.w; }
__device__ __forceinline__ float4 s4(float4 v, float s) { return make_float4(v.x*s, v.y*s, v.z*s, v.w*s); }
__device__ __forceinline__ void fma4(float4& a, float4 v, float w) {
    a.x = fmaf(v.x, w, a.x); a.y = fmaf(v.y, w, a.y);
    a.z = fmaf(v.z, w, a.z); a.w = fmaf(v.w, w, a.w);
}
__device__ __forceinline__ float wredsum(float v) {
    #pragma unroll
    for (int o = 16; o; o >>= 1) v += __shfl_xor_sync(0xffffffffu, v, o);
    return v;
}
__device__ __forceinline__ float rownorm(float4 a0, float4 a1) {
    return fmaxf(sqrtf(wredsum(d4(a0) + d4(a1))), MINNORM);
}

// ---------------- stage A: h = proj(expmap0(x)); also zero g_cnt ---------
__global__ void k_init(const float* __restrict__ x) {
    int gi = blockIdx.x * blockDim.x + threadIdx.x;
    if (gi < NN) g_cnt[gi] = 0;
    int w = threadIdx.x >> 5, lane = threadIdx.x & 31;
    int row = blockIdx.x * 8 + w;
    if (row >= NN) return;
    const float4* xp = (const float4*)x + (size_t)row * 64;
    float4 v0 = xp[lane], v1 = xp[lane + 32];
    float n = rownorm(v0, v1);
    float s = tanh_acc(n) / n;
    float4 e0 = s4(v0, s), e1 = s4(v1, s);
    float n2 = rownorm(e0, e1);
    if (n2 > MAXNORM) { float f = MAXNORM / n2; e0 = s4(e0, f); e1 = s4(e1, f); }
    float4* hp = (float4*)g_h + (size_t)row * 64;
    hp[lane] = e0; hp[lane + 32] = e1;
}

// ---------------- CSR build ----------------
__global__ void k_hist(const int* __restrict__ edst) {
    int i = blockIdx.x * blockDim.x + threadIdx.x;
    if (i < EE) atomicAdd(&g_cnt[edst[i]], 1);
}
__global__ __launch_bounds__(1024) void k_scan() {
    __shared__ int warp_sums[32];
    int tid = threadIdx.x, lane = tid & 31, wid = tid >> 5;
    int base = tid * 10;
    int v[10]; int s = 0;
    #pragma unroll
    for (int j = 0; j < 10; j++) {
        int i = base + j;
        v[j] = (i < NN) ? g_cnt[i] : 0;
        s += v[j];
    }
    int x = s;
    #pragma unroll
    for (int o = 1; o < 32; o <<= 1) {
        int y = __shfl_up_sync(0xffffffffu, x, o);
        if (lane >= o) x += y;
    }
    if (lane == 31) warp_sums[wid] = x;
    __syncthreads();
    if (wid == 0) {
        int t = warp_sums[lane];
        #pragma unroll
        for (int o = 1; o < 32; o <<= 1) {
            int y = __shfl_up_sync(0xffffffffu, t, o);
            if (lane >= o) t += y;
        }
        warp_sums[lane] = t;
    }
    __syncthreads();
    int prefix = ((wid > 0) ? warp_sums[wid - 1] : 0) + (x - s);
    #pragma unroll
    for (int j = 0; j < 10; j++) {
        int i = base + j;
        if (i < NN) { g_off[i] = prefix; g_pos[i] = prefix; }
        prefix += v[j];
    }
    if (tid == 1023) g_off[NN] = prefix;
}
__global__ void k_fill(const int* __restrict__ esrc, const int* __restrict__ edst,
                       const float* __restrict__ ew) {
    int i = blockIdx.x * blockDim.x + threadIdx.x;
    if (i < EE) {
        int d = edst[i];
        int p = atomicAdd(&g_pos[d], 1);
        g_csr_src[p] = esrc[i];
        g_csr_w[p]   = ew[i];
    }
}

// ---------------- bias ----------------
__global__ void k_bias(const float* __restrict__ b) {
    int lane = threadIdx.x;
    const float4* bp = (const float4*)b;
    float4 v0 = bp[lane], v1 = bp[lane + 32];
    float n = rownorm(v0, v1);
    float s = tanh_acc(n) / n;
    v0 = s4(v0, s); v1 = s4(v1, s);
    float n2 = rownorm(v0, v1);
    if (n2 > MAXNORM) { float f = MAXNORM / n2; v0 = s4(v0, f); v1 = s4(v1, f); }
    float y2 = wredsum(d4(v0) + d4(v1));
    ((float4*)g_bias)[lane] = v0;
    ((float4*)g_bias)[lane + 32] = v1;
    if (lane == 0) g_biasy2 = y2;
}

// ---------------- bf16 split helpers ----------------
__device__ __forceinline__ void split8(const float* f, unsigned short* hs, unsigned short* ls) {
    #pragma unroll
    for (int j = 0; j < 8; j++) {
        __nv_bfloat16 hb = __float2bfloat16(f[j]);
        float hf = __bfloat162float(hb);
        __nv_bfloat16 lb = __float2bfloat16(f[j] - hf);
        hs[j] = __bfloat16_as_ushort(hb);
        ls[j] = __bfloat16_as_ushort(lb);
    }
}
__device__ __forceinline__ uint4 pack8(const unsigned short* u) {
    uint4 r;
    r.x = (uint32_t)u[0] | ((uint32_t)u[1] << 16);
    r.y = (uint32_t)u[2] | ((uint32_t)u[3] << 16);
    r.z = (uint32_t)u[4] | ((uint32_t)u[5] << 16);
    r.w = (uint32_t)u[6] | ((uint32_t)u[7] << 16);
    return r;
}

// ---------------- convert W1,W2 -> bf16 hi/lo (once) ----------------
__global__ void k_convW(const float* __restrict__ W1, const float* __restrict__ W2) {
    int w = threadIdx.x >> 5, lane = threadIdx.x & 31;
    int row = blockIdx.x * 8 + w;         // 0..511
    if (row >= 512) return;
    const float* src = (row < 256) ? (W1 + (size_t)row * 256) : (W2 + (size_t)(row - 256) * 256);
    int layer = row >> 8;
    int lrow = row & 255;
    float f[8];
    const float4* sp = (const float4*)src;
    float4 a = sp[lane * 2], b = sp[lane * 2 + 1];
    f[0]=a.x; f[1]=a.y; f[2]=a.z; f[3]=a.w; f[4]=b.x; f[5]=b.y; f[6]=b.z; f[7]=b.w;
    unsigned short hs[8], ls[8];
    split8(f, hs, ls);
    size_t o = (size_t)layer * 65536 + (size_t)lrow * 256 + lane * 8;
    *(uint4*)(g_wh + o) = pack8(hs);
    *(uint4*)(g_wl + o) = pack8(ls);
}

// ---------------- convert g_h -> bf16 hi/lo (per layer) ----------------
__global__ void k_convA() {
    int w = threadIdx.x >> 5, lane = threadIdx.x & 31;
    int row = blockIdx.x * 8 + w;
    if (row >= NNP) return;
    size_t o = (size_t)row * 256 + lane * 8;
    if (row >= NN) {
        uint4 z = make_uint4(0, 0, 0, 0);
        *(uint4*)(g_ah + o) = z;
        *(uint4*)(g_al + o) = z;
        return;
    }
    const float* hp = g_h + (size_t)row * 256;
    float4 a = ((const float4*)hp)[lane * 2], b = ((const float4*)hp)[lane * 2 + 1];
    float f[8];
    f[0]=a.x; f[1]=a.y; f[2]=a.z; f[3]=a.w; f[4]=b.x; f[5]=b.y; f[6]=b.z; f[7]=b.w;
    unsigned short hs[8], ls[8];
    split8(f, hs, ls);
    *(uint4*)(g_ah + o) = pack8(hs);
    *(uint4*)(g_al + o) = pack8(ls);
}

// ---------------- HMMA bf16-split GEMM: g_mx = g_h @ W^T ----------------
// CTA tile 128x128, 8 warps (4m x 2n), warp tile 32x64, K chunks of 64.
// smem tiles [row][64 bf16] = 128B rows, 16B-chunk XOR swizzle: c' = c ^ (r&7).
__device__ __forceinline__ void ldsm4(uint32_t addr, uint32_t* r) {
    asm volatile("ldmatrix.sync.aligned.m8n8.x4.shared.b16 {%0,%1,%2,%3}, [%4];"
                 : "=r"(r[0]), "=r"(r[1]), "=r"(r[2]), "=r"(r[3]) : "r"(addr));
}
__device__ __forceinline__ void mma16816(float* c, const uint32_t* a, uint32_t b0, uint32_t b1) {
    asm volatile(
        "mma.sync.aligned.m16n8k16.row.col.f32.bf16.bf16.f32 "
        "{%0,%1,%2,%3}, {%4,%5,%6,%7}, {%8,%9}, {%0,%1,%2,%3};"
        : "+f"(c[0]), "+f"(c[1]), "+f"(c[2]), "+f"(c[3])
        : "r"(a[0]), "r"(a[1]), "r"(a[2]), "r"(a[3]), "r"(b0), "r"(b1));
}

#define HS_AH 0
#define HS_AL 16384
#define HS_BH 32768
#define HS_BL 49152
#define HS_TOTAL 65536

__global__ __launch_bounds__(256, 1) void k_hmma(int layer) {
    extern __shared__ __align__(1024) char smem[];
    uint32_t sb;
    asm("{ .reg .u64 t; cvta.to.shared.u64 t, %1; cvt.u32.u64 %0, t; }" : "=r"(sb) : "l"(smem));
    int tid = threadIdx.x, lane = tid & 31, wid = tid >> 5;
    int wm = wid & 3, wn = wid >> 2;
    int m0 = blockIdx.x * 128, n0 = blockIdx.y * 128;
    const __nv_bfloat16* wh = g_wh + (size_t)layer * 65536;
    const __nv_bfloat16* wl = g_wl + (size_t)layer * 65536;

    float acc[2][8][4];
    #pragma unroll
    for (int mt = 0; mt < 2; mt++)
        #pragma unroll
        for (int nt = 0; nt < 8; nt++)
            #pragma unroll
            for (int q = 0; q < 4; q++) acc[mt][nt][q] = 0.f;

    for (int ch = 0; ch < 4; ch++) {
        int k0 = ch * 64;
        #pragma unroll
        for (int i = 0; i < 4; i++) {
            int idx = tid + 256 * i;            // 0..1023
            int r = idx >> 3, c = idx & 7;
            uint32_t dst = (uint32_t)(r * 8 + (c ^ (r & 7))) * 16;
            *(uint4*)(smem + HS_AH + dst) = *(const uint4*)(g_ah + (size_t)(m0 + r) * 256 + k0 + c * 8);
            *(uint4*)(smem + HS_AL + dst) = *(const uint4*)(g_al + (size_t)(m0 + r) * 256 + k0 + c * 8);
            *(uint4*)(smem + HS_BH + dst) = *(const uint4*)(wh + (size_t)(n0 + r) * 256 + k0 + c * 8);
            *(uint4*)(smem + HS_BL + dst) = *(const uint4*)(wl + (size_t)(n0 + r) * 256 + k0 + c * 8);
        }
        __syncthreads();
        #pragma unroll
        for (int kk = 0; kk < 4; kk++) {
            uint32_t ah[2][4], al[2][4];
            #pragma unroll
            for (int mt = 0; mt < 2; mt++) {
                int row = wm * 32 + mt * 16 + (lane & 15);
                int ck = kk * 2 + (lane >> 4);
                uint32_t off = (uint32_t)(row * 8 + (ck ^ (row & 7))) * 16;
                ldsm4(sb + HS_AH + off, ah[mt]);
                ldsm4(sb + HS_AL + off, al[mt]);
            }
            #pragma unroll
            for (int ng = 0; ng < 4; ng++) {
                int row = wn * 64 + ng * 16 + ((lane >> 4) << 3) + (lane & 7);
                int ck = kk * 2 + ((lane >> 3) & 1);
                uint32_t off = (uint32_t)(row * 8 + (ck ^ (row & 7))) * 16;
                uint32_t bh[4], bl[4];
                ldsm4(sb + HS_BH + off, bh);
                ldsm4(sb + HS_BL + off, bl);
                #pragma unroll
                for (int mt = 0; mt < 2; mt++) {
                    mma16816(acc[mt][ng*2+0], ah[mt], bh[0], bh[1]);
                    mma16816(acc[mt][ng*2+0], ah[mt], bl[0], bl[1]);
                    mma16816(acc[mt][ng*2+0], al[mt], bh[0], bh[1]);
                    mma16816(acc[mt][ng*2+1], ah[mt], bh[2], bh[3]);
                    mma16816(acc[mt][ng*2+1], ah[mt], bl[2], bl[3]);
                    mma16816(acc[mt][ng*2+1], al[mt], bh[2], bh[3]);
                }
            }
        }
        __syncthreads();
    }

    // store: d0,d1 -> row lane/4, cols 2*(lane%4)+{0,1}; d2,d3 -> row+8
    #pragma unroll
    for (int mt = 0; mt < 2; mt++) {
        int mrow0 = m0 + wm * 32 + mt * 16 + (lane >> 2);
        #pragma unroll
        for (int nt = 0; nt < 8; nt++) {
            int col = n0 + wn * 64 + nt * 8 + 2 * (lane & 3);
            if (mrow0 < NN)
                *(float2*)(g_mx + (size_t)mrow0 * 256 + col) = make_float2(acc[mt][nt][0], acc[mt][nt][1]);
            if (mrow0 + 8 < NN)
                *(float2*)(g_mx + (size_t)(mrow0 + 8) * 256 + col) = make_float2(acc[mt][nt][2], acc[mt][nt][3]);
        }
    }
}

// ---------------- fused HypLinear tail + logmap0 → g_xt ----------------
__global__ void k_pre() {
    int w = threadIdx.x >> 5, lane = threadIdx.x & 31;
    int row = blockIdx.x * 8 + w;
    if (row >= NN) return;
    const float4* hp = (const float4*)g_h  + (size_t)row * 64;
    const float4* mp = (const float4*)g_mx + (size_t)row * 64;
    float4 h0 = hp[lane], h1 = hp[lane + 32];
    float4 m0 = mp[lane], m1 = mp[lane + 32];

    float xn  = rownorm(h0, h1);
    float mn2 = wredsum(d4(m0) + d4(m1));
    bool  zero = (mn2 == 0.f);
    float mxn = fmaxf(sqrtf(mn2), MINNORM);
    float arg = mxn / xn * atanh_clip(xn);
    float sc  = tanh_acc(arg) / mxn;
    if (zero) sc = 0.f;
    float4 r0 = s4(m0, sc), r1 = s4(m1, sc);
    float rn = rownorm(r0, r1);
    if (rn > MAXNORM) { float f = MAXNORM / rn; r0 = s4(r0, f); r1 = s4(r1, f); }

    float4 b0 = ((const float4*)g_bias)[lane];
    float4 b1 = ((const float4*)g_bias)[lane + 32];
    float x2 = wredsum(d4(r0) + d4(r1));
    float xy = wredsum(dd4(r0, b0) + dd4(r1, b1));
    float y2 = g_biasy2;
    float ca = 1.f + 2.f * xy + y2;
    float cb = 1.f - x2;
    float den = fmaxf(1.f + 2.f * xy + x2 * y2, MINNORM);
    float4 q0, q1;
    q0.x = (ca*r0.x + cb*b0.x)/den; q0.y = (ca*r0.y + cb*b0.y)/den;
    q0.z = (ca*r0.z + cb*b0.z)/den; q0.w = (ca*r0.w + cb*b0.w)/den;
    q1.x = (ca*r1.x + cb*b1.x)/den; q1.y = (ca*r1.y + cb*b1.y)/den;
    q1.z = (ca*r1.z + cb*b1.z)/den; q1.w = (ca*r1.w + cb*b1.w)/den;
    float qn = rownorm(q0, q1);
    if (qn > MAXNORM) { float f = MAXNORM / qn; q0 = s4(q0, f); q1 = s4(q1, f); }

    float pn = rownorm(q0, q1);
    float ls = atanh_clip(pn) / pn;
    q0 = s4(q0, ls); q1 = s4(q1, ls);

    float4* xp = (float4*)g_xt + (size_t)row * 64;
    xp[lane] = q0; xp[lane + 32] = q1;
}

// ---------------- fused CSR aggregation + HypAgg/HypAct tail -------------
__global__ __launch_bounds__(256) void k_aggpost(float* __restrict__ out, int write_out) {
    int w = threadIdx.x >> 5, lane = threadIdx.x & 31;
    int row = blockIdx.x * 8 + w;
    if (row >= NN) return;
    int beg = g_off[row], end = g_off[row + 1];

    float4 a0 = make_float4(0.f, 0.f, 0.f, 0.f);
    float4 a1 = make_float4(0.f, 0.f, 0.f, 0.f);

    for (int c = beg; c < end; c += 32) {
        int n = end - c; if (n > 32) n = 32;
        int   sv = 0; float wv = 0.f;
        if (lane < n) {
            sv = __ldg(&g_csr_src[c + lane]);
            wv = __ldg(&g_csr_w[c + lane]);
        }
        int j = 0;
        for (; j + 1 < n; j += 2) {
            int   s0 = __shfl_sync(0xffffffffu, sv, j);
            int   s1 = __shfl_sync(0xffffffffu, sv, j + 1);
            float w0 = __shfl_sync(0xffffffffu, wv, j);
            float w1 = __shfl_sync(0xffffffffu, wv, j + 1);
            const float4* p0 = (const float4*)g_xt + (size_t)s0 * 64;
            const float4* p1 = (const float4*)g_xt + (size_t)s1 * 64;
            float4 u0 = __ldg(&p0[lane]);
            float4 u1 = __ldg(&p0[lane + 32]);
            float4 t0 = __ldg(&p1[lane]);
            float4 t1 = __ldg(&p1[lane + 32]);
            fma4(a0, u0, w0); fma4(a1, u1, w0);
            fma4(a0, t0, w1); fma4(a1, t1, w1);
        }
        if (j < n) {
            int   s0 = __shfl_sync(0xffffffffu, sv, j);
            float w0 = __shfl_sync(0xffffffffu, wv, j);
            const float4* p0 = (const float4*)g_xt + (size_t)s0 * 64;
            float4 u0 = __ldg(&p0[lane]);
            float4 u1 = __ldg(&p0[lane + 32]);
            fma4(a0, u0, w0); fma4(a1, u1, w0);
        }
    }

    float n1 = rownorm(a0, a1);
    float s = tanh_acc(n1) / n1;
    float4 e0 = s4(a0, s), e1 = s4(a1, s);
    float n2 = rownorm(e0, e1);
    if (n2 > MAXNORM) { float f = MAXNORM / n2; e0 = s4(e0, f); e1 = s4(e1, f); }
    float pn = rownorm(e0, e1);
    float ls = atanh_clip(pn) / pn;
    float4 u0, u1;
    u0.x = fmaxf(e0.x * ls, 0.f); u0.y = fmaxf(e0.y * ls, 0.f);
    u0.z = fmaxf(e0.z * ls, 0.f); u0.w = fmaxf(e0.w * ls, 0.f);
    u1.x = fmaxf(e1.x * ls, 0.f); u1.y = fmaxf(e1.y * ls, 0.f);
    u1.z = fmaxf(e1.z * ls, 0.f); u1.w = fmaxf(e1.w * ls, 0.f);
    float un = rownorm(u0, u1);
    float s2 = tanh_acc(un) / un;
    float4 o0 = s4(u0, s2), o1 = s4(u1, s2);
    float n3 = rownorm(o0, o1);
    if (n3 > MAXNORM) { float f = MAXNORM / n3; o0 = s4(o0, f); o1 = s4(o1, f); }

    float4* dst = write_out ? ((float4*)out + (size_t)row * 64)
                            : ((float4*)g_h + (size_t)row * 64);
    dst[lane] = o0; dst[lane + 32] = o1;
}

// ---------------- launch ----------------
extern "C" void kernel_launch(void* const* d_in, const int* in_sizes, int n_in,
                              void* d_out, int out_size) {
    const float* x    = (const float*)d_in[0];
    const float* W1   = (const float*)d_in[1];
    const float* b1   = (const float*)d_in[2];
    const float* W2   = (const float*)d_in[3];
    const float* b2   = (const float*)d_in[4];
    const float* ew   = (const float*)d_in[5];
    const int*   esrc = (const int*)d_in[6];
    const int*   edst = (const int*)d_in[7];
    float* out = (float*)d_out;
    (void)in_sizes; (void)n_in; (void)out_size;

    const int rowBlocks  = (NN + 7) / 8;
    const int convBlocks = NNP / 8;
    const int eBlocks    = (EE + 255) / 256;
    dim3 hmmaGrid(GB, 2);

    cudaFuncSetAttribute(k_hmma, cudaFuncAttributeMaxDynamicSharedMemorySize, HS_TOTAL);

    k_init<<<rowBlocks, 256>>>(x);
    k_hist<<<eBlocks, 256>>>(edst);
    k_scan<<<1, 1024>>>();
    k_fill<<<eBlocks, 256>>>(esrc, edst, ew);
    k_convW<<<64, 256>>>(W1, W2);

    // layer 1
    k_bias<<<1, 32>>>(b1);
    k_convA<<<convBlocks, 256>>>();
    k_hmma<<<hmmaGrid, 256, HS_TOTAL>>>(0);
    k_pre<<<rowBlocks, 256>>>();
    k_aggpost<<<rowBlocks, 256>>>(out, 0);

    // layer 2
    k_bias<<<1, 32>>>(b2);
    k_convA<<<convBlocks, 256>>>();
    k_hmma<<<hmmaGrid, 256, HS_TOTAL>>>(1);
    k_pre<<<rowBlocks, 256>>>();
    k_aggpost<<<rowBlocks, 256>>>(out, 1);
}

// round 14
// speedup vs baseline: 1.4526x; 1.0974x over previous
#include <cuda_runtime.h>
#include <cuda_bf16.h>
#include <cuda_fp16.h>
#include <math.h>
#include <stdint.h>

// ---------------- problem constants ----------------
#define NN 10000
#define DD 256
#define EE 320000
#define MAXNORM 0.996f
#define MINNORM 1e-15f
#define ATANH_CLIP (1.0f - 1e-7f)

#define GB 79
#define NNP (GB * 128)    // 10112 padded rows

// ---------------- scratch ----------------
__device__ float g_h  [NN * DD];
__device__ float g_mx [NN * DD];
__device__ __half g_xth[NN * DD];
__device__ float g_bias[DD];
__device__ float g_biasy2;
__device__ __nv_bfloat16 g_ah[NNP * DD];
__device__ __nv_bfloat16 g_al[NNP * DD];
__device__ __nv_bfloat16 g_wh[2 * DD * DD];
__device__ __nv_bfloat16 g_wl[2 * DD * DD];
// CSR-by-dst
__device__ int   g_cnt[NN];
__device__ int   g_off[NN + 1];
__device__ int   g_pos[NN];
__device__ int2  g_csr_pair[EE];   // (src, w-bits)

// ---------------- numerics ----------------
__device__ __forceinline__ float tanh_acc(float x) {
    float a = fabsf(x);
    if (a > 15.f) return copysignf(1.f, x);
    float s = expm1f(2.f * a);
    float r = s / (s + 2.f);
    return copysignf(r, x);
}
__device__ __forceinline__ float atanh_clip(float r) {
    float a = fminf(r, ATANH_CLIP);
    return 0.5f * log1pf(2.f * a / (1.f - a));
}

// ---------------- helpers ----------------
__device__ __forceinline__ float d4(float4 v)  { return v.x*v.x + v.y*v.y + v.z*v.z + v.w*v.w; }
__device__ __forceinline__ float dd4(float4 a, float4 b) { return a.x*b.x + a.y*b.y + a.z*b.z + a.w*b.w; }
__device__ __forceinline__ float4 s4(float4 v, float s) { return make_float4(v.x*s, v.y*s, v.z*s, v.w*s); }
__device__ __forceinline__ float wredsum(float v) {
    #pragma unroll
    for (int o = 16; o; o >>= 1) v += __shfl_xor_sync(0xffffffffu, v, o);
    return v;
}
__device__ __forceinline__ float rownorm(float4 a0, float4 a1) {
    return fmaxf(sqrtf(wredsum(d4(a0) + d4(a1))), MINNORM);
}

// ---------------- bf16 split helpers ----------------
__device__ __forceinline__ uint4 pack8(const unsigned short* u) {
    uint4 r;
    r.x = (uint32_t)u[0] | ((uint32_t)u[1] << 16);
    r.y = (uint32_t)u[2] | ((uint32_t)u[3] << 16);
    r.z = (uint32_t)u[4] | ((uint32_t)u[5] << 16);
    r.w = (uint32_t)u[6] | ((uint32_t)u[7] << 16);
    return r;
}
// write bf16 hi/lo split of 8 floats (cols lane*8..+7) for row
__device__ __forceinline__ void write_split(int row, int lane, const float* f) {
    unsigned short hs[8], ls[8];
    #pragma unroll
    for (int j = 0; j < 8; j++) {
        __nv_bfloat16 hb = __float2bfloat16(f[j]);
        float hf = __bfloat162float(hb);
        __nv_bfloat16 lb = __float2bfloat16(f[j] - hf);
        hs[j] = __bfloat16_as_ushort(hb);
        ls[j] = __bfloat16_as_ushort(lb);
    }
    size_t o = (size_t)row * 256 + lane * 8;
    *(uint4*)(g_ah + o) = pack8(hs);
    *(uint4*)(g_al + o) = pack8(ls);
}

// ---------------- stage A: h = proj(expmap0(x)); zero cnt + pad rows -----
__global__ void k_init(const float* __restrict__ x) {
    int gi = blockIdx.x * blockDim.x + threadIdx.x;
    if (gi < NN) g_cnt[gi] = 0;
    if (gi < (NNP - NN) * 32) {           // zero pad rows of g_ah/g_al
        uint4 z = make_uint4(0, 0, 0, 0);
        ((uint4*)(g_ah + (size_t)NN * 256))[gi] = z;
        ((uint4*)(g_al + (size_t)NN * 256))[gi] = z;
    }
    int lane = threadIdx.x & 31;
    int row = blockIdx.x * 8 + (threadIdx.x >> 5);
    if (row >= NN) return;
    const float4* xp = (const float4*)(x + (size_t)row * 256);
    float4 v0 = xp[2 * lane], v1 = xp[2 * lane + 1];   // cols lane*8..+7
    float n = rownorm(v0, v1);
    float s = tanh_acc(n) / n;
    float4 e0 = s4(v0, s), e1 = s4(v1, s);
    float n2 = rownorm(e0, e1);
    if (n2 > MAXNORM) { float f = MAXNORM / n2; e0 = s4(e0, f); e1 = s4(e1, f); }
    float4* hp = (float4*)(g_h + (size_t)row * 256);
    hp[2 * lane] = e0; hp[2 * lane + 1] = e1;
    float f[8] = {e0.x, e0.y, e0.z, e0.w, e1.x, e1.y, e1.z, e1.w};
    write_split(row, lane, f);
}

// ---------------- CSR build ----------------
__global__ void k_hist(const int* __restrict__ edst) {
    int i = blockIdx.x * blockDim.x + threadIdx.x;
    if (i < EE) atomicAdd(&g_cnt[edst[i]], 1);
}
__global__ __launch_bounds__(1024) void k_scan() {
    __shared__ int warp_sums[32];
    int tid = threadIdx.x, lane = tid & 31, wid = tid >> 5;
    int base = tid * 10;
    int v[10]; int s = 0;
    #pragma unroll
    for (int j = 0; j < 10; j++) {
        int i = base + j;
        v[j] = (i < NN) ? g_cnt[i] : 0;
        s += v[j];
    }
    int x = s;
    #pragma unroll
    for (int o = 1; o < 32; o <<= 1) {
        int y = __shfl_up_sync(0xffffffffu, x, o);
        if (lane >= o) x += y;
    }
    if (lane == 31) warp_sums[wid] = x;
    __syncthreads();
    if (wid == 0) {
        int t = warp_sums[lane];
        #pragma unroll
        for (int o = 1; o < 32; o <<= 1) {
            int y = __shfl_up_sync(0xffffffffu, t, o);
            if (lane >= o) t += y;
        }
        warp_sums[lane] = t;
    }
    __syncthreads();
    int prefix = ((wid > 0) ? warp_sums[wid - 1] : 0) + (x - s);
    #pragma unroll
    for (int j = 0; j < 10; j++) {
        int i = base + j;
        if (i < NN) { g_off[i] = prefix; g_pos[i] = prefix; }
        prefix += v[j];
    }
    if (tid == 1023) g_off[NN] = prefix;
}
__global__ void k_fill(const int* __restrict__ esrc, const int* __restrict__ edst,
                       const float* __restrict__ ew) {
    int i = blockIdx.x * blockDim.x + threadIdx.x;
    if (i < EE) {
        int d = edst[i];
        int p = atomicAdd(&g_pos[d], 1);
        g_csr_pair[p] = make_int2(esrc[i], __float_as_int(ew[i]));
    }
}

// ---------------- bias ----------------
__global__ void k_bias(const float* __restrict__ b) {
    int lane = threadIdx.x;
    const float4* bp = (const float4*)b;
    float4 v0 = bp[lane], v1 = bp[lane + 32];
    float n = rownorm(v0, v1);
    float s = tanh_acc(n) / n;
    v0 = s4(v0, s); v1 = s4(v1, s);
    float n2 = rownorm(v0, v1);
    if (n2 > MAXNORM) { float f = MAXNORM / n2; v0 = s4(v0, f); v1 = s4(v1, f); }
    float y2 = wredsum(d4(v0) + d4(v1));
    ((float4*)g_bias)[lane] = v0;
    ((float4*)g_bias)[lane + 32] = v1;
    if (lane == 0) g_biasy2 = y2;
}

// ---------------- convert W1,W2 -> bf16 hi/lo (once) ----------------
__global__ void k_convW(const float* __restrict__ W1, const float* __restrict__ W2) {
    int w = threadIdx.x >> 5, lane = threadIdx.x & 31;
    int row = blockIdx.x * 8 + w;         // 0..511
    if (row >= 512) return;
    const float* src = (row < 256) ? (W1 + (size_t)row * 256) : (W2 + (size_t)(row - 256) * 256);
    int layer = row >> 8;
    int lrow = row & 255;
    const float4* sp = (const float4*)src;
    float4 a = sp[lane * 2], b = sp[lane * 2 + 1];
    float f[8] = {a.x, a.y, a.z, a.w, b.x, b.y, b.z, b.w};
    unsigned short hs[8], ls[8];
    #pragma unroll
    for (int j = 0; j < 8; j++) {
        __nv_bfloat16 hb = __float2bfloat16(f[j]);
        float hf = __bfloat162float(hb);
        __nv_bfloat16 lb = __float2bfloat16(f[j] - hf);
        hs[j] = __bfloat16_as_ushort(hb);
        ls[j] = __bfloat16_as_ushort(lb);
    }
    size_t o = (size_t)layer * 65536 + (size_t)lrow * 256 + lane * 8;
    *(uint4*)(g_wh + o) = pack8(hs);
    *(uint4*)(g_wl + o) = pack8(ls);
}

// ---------------- HMMA bf16-split GEMM: g_mx = g_h @ W^T ----------------
__device__ __forceinline__ void ldsm4(uint32_t addr, uint32_t* r) {
    asm volatile("ldmatrix.sync.aligned.m8n8.x4.shared.b16 {%0,%1,%2,%3}, [%4];"
                 : "=r"(r[0]), "=r"(r[1]), "=r"(r[2]), "=r"(r[3]) : "r"(addr));
}
__device__ __forceinline__ void mma16816(float* c, const uint32_t* a, uint32_t b0, uint32_t b1) {
    asm volatile(
        "mma.sync.aligned.m16n8k16.row.col.f32.bf16.bf16.f32 "
        "{%0,%1,%2,%3}, {%4,%5,%6,%7}, {%8,%9}, {%0,%1,%2,%3};"
        : "+f"(c[0]), "+f"(c[1]), "+f"(c[2]), "+f"(c[3])
        : "r"(a[0]), "r"(a[1]), "r"(a[2]), "r"(a[3]), "r"(b0), "r"(b1));
}

#define HS_AH 0
#define HS_AL 16384
#define HS_BH 32768
#define HS_BL 49152
#define HS_TOTAL 65536

__global__ __launch_bounds__(256, 1) void k_hmma(int layer) {
    extern __shared__ __align__(1024) char smem[];
    uint32_t sb;
    asm("{ .reg .u64 t; cvta.to.shared.u64 t, %1; cvt.u32.u64 %0, t; }" : "=r"(sb) : "l"(smem));
    int tid = threadIdx.x, lane = tid & 31, wid = tid >> 5;
    int wm = wid & 3, wn = wid >> 2;
    int m0 = blockIdx.x * 128, n0 = blockIdx.y * 128;
    const __nv_bfloat16* wh = g_wh + (size_t)layer * 65536;
    const __nv_bfloat16* wl = g_wl + (size_t)layer * 65536;

    float acc[2][8][4];
    #pragma unroll
    for (int mt = 0; mt < 2; mt++)
        #pragma unroll
        for (int nt = 0; nt < 8; nt++)
            #pragma unroll
            for (int q = 0; q < 4; q++) acc[mt][nt][q] = 0.f;

    for (int ch = 0; ch < 4; ch++) {
        int k0 = ch * 64;
        #pragma unroll
        for (int i = 0; i < 4; i++) {
            int idx = tid + 256 * i;            // 0..1023
            int r = idx >> 3, c = idx & 7;
            uint32_t dst = (uint32_t)(r * 8 + (c ^ (r & 7))) * 16;
            *(uint4*)(smem + HS_AH + dst) = *(const uint4*)(g_ah + (size_t)(m0 + r) * 256 + k0 + c * 8);
            *(uint4*)(smem + HS_AL + dst) = *(const uint4*)(g_al + (size_t)(m0 + r) * 256 + k0 + c * 8);
            *(uint4*)(smem + HS_BH + dst) = *(const uint4*)(wh + (size_t)(n0 + r) * 256 + k0 + c * 8);
            *(uint4*)(smem + HS_BL + dst) = *(const uint4*)(wl + (size_t)(n0 + r) * 256 + k0 + c * 8);
        }
        __syncthreads();
        #pragma unroll
        for (int kk = 0; kk < 4; kk++) {
            uint32_t ah[2][4], al[2][4];
            #pragma unroll
            for (int mt = 0; mt < 2; mt++) {
                int row = wm * 32 + mt * 16 + (lane & 15);
                int ck = kk * 2 + (lane >> 4);
                uint32_t off = (uint32_t)(row * 8 + (ck ^ (row & 7))) * 16;
                ldsm4(sb + HS_AH + off, ah[mt]);
                ldsm4(sb + HS_AL + off, al[mt]);
            }
            #pragma unroll
            for (int ng = 0; ng < 4; ng++) {
                int row = wn * 64 + ng * 16 + ((lane >> 4) << 3) + (lane & 7);
                int ck = kk * 2 + ((lane >> 3) & 1);
                uint32_t off = (uint32_t)(row * 8 + (ck ^ (row & 7))) * 16;
                uint32_t bh[4], bl[4];
                ldsm4(sb + HS_BH + off, bh);
                ldsm4(sb + HS_BL + off, bl);
                #pragma unroll
                for (int mt = 0; mt < 2; mt++) {
                    mma16816(acc[mt][ng*2+0], ah[mt], bh[0], bh[1]);
                    mma16816(acc[mt][ng*2+0], ah[mt], bl[0], bl[1]);
                    mma16816(acc[mt][ng*2+0], al[mt], bh[0], bh[1]);
                    mma16816(acc[mt][ng*2+1], ah[mt], bh[2], bh[3]);
                    mma16816(acc[mt][ng*2+1], ah[mt], bl[2], bl[3]);
                    mma16816(acc[mt][ng*2+1], al[mt], bh[2], bh[3]);
                }
            }
        }
        __syncthreads();
    }

    #pragma unroll
    for (int mt = 0; mt < 2; mt++) {
        int mrow0 = m0 + wm * 32 + mt * 16 + (lane >> 2);
        #pragma unroll
        for (int nt = 0; nt < 8; nt++) {
            int col = n0 + wn * 64 + nt * 8 + 2 * (lane & 3);
            if (mrow0 < NN)
                *(float2*)(g_mx + (size_t)mrow0 * 256 + col) = make_float2(acc[mt][nt][0], acc[mt][nt][1]);
            if (mrow0 + 8 < NN)
                *(float2*)(g_mx + (size_t)(mrow0 + 8) * 256 + col) = make_float2(acc[mt][nt][2], acc[mt][nt][3]);
        }
    }
}

// ---------------- fused HypLinear tail + logmap0 → g_xth (fp16) ----------
__global__ void k_pre() {
    int lane = threadIdx.x & 31;
    int row = blockIdx.x * 8 + (threadIdx.x >> 5);
    if (row >= NN) return;
    const float4* hp = (const float4*)(g_h  + (size_t)row * 256);
    const float4* mp = (const float4*)(g_mx + (size_t)row * 256);
    float4 h0 = hp[2*lane], h1 = hp[2*lane+1];
    float4 m0 = mp[2*lane], m1 = mp[2*lane+1];

    float xn  = rownorm(h0, h1);
    float mn2 = wredsum(d4(m0) + d4(m1));
    bool  zero = (mn2 == 0.f);
    float mxn = fmaxf(sqrtf(mn2), MINNORM);
    float arg = mxn / xn * atanh_clip(xn);
    float sc  = tanh_acc(arg) / mxn;
    if (zero) sc = 0.f;
    float4 r0 = s4(m0, sc), r1 = s4(m1, sc);
    float rn = rownorm(r0, r1);
    if (rn > MAXNORM) { float f = MAXNORM / rn; r0 = s4(r0, f); r1 = s4(r1, f); }

    const float4* gb = (const float4*)g_bias;
    float4 b0 = gb[2*lane], b1 = gb[2*lane+1];
    float x2 = wredsum(d4(r0) + d4(r1));
    float xy = wredsum(dd4(r0, b0) + dd4(r1, b1));
    float y2 = g_biasy2;
    float ca = 1.f + 2.f * xy + y2;
    float cb = 1.f - x2;
    float den = fmaxf(1.f + 2.f * xy + x2 * y2, MINNORM);
    float4 q0, q1;
    q0.x = (ca*r0.x + cb*b0.x)/den; q0.y = (ca*r0.y + cb*b0.y)/den;
    q0.z = (ca*r0.z + cb*b0.z)/den; q0.w = (ca*r0.w + cb*b0.w)/den;
    q1.x = (ca*r1.x + cb*b1.x)/den; q1.y = (ca*r1.y + cb*b1.y)/den;
    q1.z = (ca*r1.z + cb*b1.z)/den; q1.w = (ca*r1.w + cb*b1.w)/den;
    float qn = rownorm(q0, q1);
    if (qn > MAXNORM) { float f = MAXNORM / qn; q0 = s4(q0, f); q1 = s4(q1, f); }

    float pn = rownorm(q0, q1);
    float ls = atanh_clip(pn) / pn;
    q0 = s4(q0, ls); q1 = s4(q1, ls);

    // pack 8 floats -> 8 halves -> uint4
    __half2 hx = __float22half2_rn(make_float2(q0.x, q0.y));
    __half2 hy = __float22half2_rn(make_float2(q0.z, q0.w));
    __half2 hz = __float22half2_rn(make_float2(q1.x, q1.y));
    __half2 hw = __float22half2_rn(make_float2(q1.z, q1.w));
    uint4 pk;
    pk.x = *(uint32_t*)&hx; pk.y = *(uint32_t*)&hy;
    pk.z = *(uint32_t*)&hz; pk.w = *(uint32_t*)&hw;
    *(uint4*)(g_xth + (size_t)row * 256 + lane * 8) = pk;
}

// ---------------- fused CSR aggregation (fp16 gather) + HypAgg/HypAct ----
__global__ __launch_bounds__(256) void k_aggpost(float* __restrict__ out, int write_out) {
    int lane = threadIdx.x & 31;
    int row = blockIdx.x * 8 + (threadIdx.x >> 5);
    if (row >= NN) return;
    int beg = g_off[row], end = g_off[row + 1];

    float acc[8];
    #pragma unroll
    for (int j = 0; j < 8; j++) acc[j] = 0.f;

    for (int c = beg; c < end; c += 32) {
        int n = end - c; if (n > 32) n = 32;
        int2 pv = make_int2(0, 0);
        if (lane < n) pv = __ldg(&g_csr_pair[c + lane]);
        int j = 0;
        for (; j + 1 < n; j += 2) {
            int   s0 = __shfl_sync(0xffffffffu, pv.x, j);
            int   s1 = __shfl_sync(0xffffffffu, pv.x, j + 1);
            float w0 = __int_as_float(__shfl_sync(0xffffffffu, pv.y, j));
            float w1 = __int_as_float(__shfl_sync(0xffffffffu, pv.y, j + 1));
            uint4 u = __ldg((const uint4*)(g_xth + (size_t)s0 * 256) + lane);
            uint4 t = __ldg((const uint4*)(g_xth + (size_t)s1 * 256) + lane);
            const __half2* uh = (const __half2*)&u;
            const __half2* th = (const __half2*)&t;
            #pragma unroll
            for (int q = 0; q < 4; q++) {
                float2 fu = __half22float2(uh[q]);
                float2 ft = __half22float2(th[q]);
                acc[q*2+0] = fmaf(fu.x, w0, acc[q*2+0]);
                acc[q*2+1] = fmaf(fu.y, w0, acc[q*2+1]);
                acc[q*2+0] = fmaf(ft.x, w1, acc[q*2+0]);
                acc[q*2+1] = fmaf(ft.y, w1, acc[q*2+1]);
            }
        }
        if (j < n) {
            int   s0 = __shfl_sync(0xffffffffu, pv.x, j);
            float w0 = __int_as_float(__shfl_sync(0xffffffffu, pv.y, j));
            uint4 u = __ldg((const uint4*)(g_xth + (size_t)s0 * 256) + lane);
            const __half2* uh = (const __half2*)&u;
            #pragma unroll
            for (int q = 0; q < 4; q++) {
                float2 fu = __half22float2(uh[q]);
                acc[q*2+0] = fmaf(fu.x, w0, acc[q*2+0]);
                acc[q*2+1] = fmaf(fu.y, w0, acc[q*2+1]);
            }
        }
    }

    float4 a0 = make_float4(acc[0], acc[1], acc[2], acc[3]);
    float4 a1 = make_float4(acc[4], acc[5], acc[6], acc[7]);

    float n1 = rownorm(a0, a1);
    float s = tanh_acc(n1) / n1;
    float4 e0 = s4(a0, s), e1 = s4(a1, s);
    float n2 = rownorm(e0, e1);
    if (n2 > MAXNORM) { float f = MAXNORM / n2; e0 = s4(e0, f); e1 = s4(e1, f); }
    float pn = rownorm(e0, e1);
    float ls = atanh_clip(pn) / pn;
    float4 u0, u1;
    u0.x = fmaxf(e0.x * ls, 0.f); u0.y = fmaxf(e0.y * ls, 0.f);
    u0.z = fmaxf(e0.z * ls, 0.f); u0.w = fmaxf(e0.w * ls, 0.f);
    u1.x = fmaxf(e1.x * ls, 0.f); u1.y = fmaxf(e1.y * ls, 0.f);
    u1.z = fmaxf(e1.z * ls, 0.f); u1.w = fmaxf(e1.w * ls, 0.f);
    float un = rownorm(u0, u1);
    float s2 = tanh_acc(un) / un;
    float4 o0 = s4(u0, s2), o1 = s4(u1, s2);
    float n3 = rownorm(o0, o1);
    if (n3 > MAXNORM) { float f = MAXNORM / n3; o0 = s4(o0, f); o1 = s4(o1, f); }

    if (write_out) {
        float4* dst = (float4*)(out + (size_t)row * 256);
        dst[2*lane] = o0; dst[2*lane+1] = o1;
    } else {
        float4* dst = (float4*)(g_h + (size_t)row * 256);
        dst[2*lane] = o0; dst[2*lane+1] = o1;
        float f[8] = {o0.x, o0.y, o0.z, o0.w, o1.x, o1.y, o1.z, o1.w};
        write_split(row, lane, f);
    }
}

// ---------------- launch ----------------
extern "C" void kernel_launch(void* const* d_in, const int* in_sizes, int n_in,
                              void* d_out, int out_size) {
    const float* x    = (const float*)d_in[0];
    const float* W1   = (const float*)d_in[1];
    const float* b1   = (const float*)d_in[2];
    const float* W2   = (const float*)d_in[3];
    const float* b2   = (const float*)d_in[4];
    const float* ew   = (const float*)d_in[5];
    const int*   esrc = (const int*)d_in[6];
    const int*   edst = (const int*)d_in[7];
    float* out = (float*)d_out;
    (void)in_sizes; (void)n_in; (void)out_size;

    const int rowBlocks = (NN + 7) / 8;
    const int eBlocks   = (EE + 255) / 256;
    dim3 hmmaGrid(GB, 2);

    cudaFuncSetAttribute(k_hmma, cudaFuncAttributeMaxDynamicSharedMemorySize, HS_TOTAL);

    k_init<<<rowBlocks, 256>>>(x);
    k_hist<<<eBlocks, 256>>>(edst);
    k_scan<<<1, 1024>>>();
    k_fill<<<eBlocks, 256>>>(esrc, edst, ew);
    k_convW<<<64, 256>>>(W1, W2);

    // layer 1
    k_bias<<<1, 32>>>(b1);
    k_hmma<<<hmmaGrid, 256, HS_TOTAL>>>(0);
    k_pre<<<rowBlocks, 256>>>();
    k_aggpost<<<rowBlocks, 256>>>(out, 0);

    // layer 2
    k_bias<<<1, 32>>>(b2);
    k_hmma<<<hmmaGrid, 256, HS_TOTAL>>>(1);
    k_pre<<<rowBlocks, 256>>>();
    k_aggpost<<<rowBlocks, 256>>>(out, 1);
}

// round 15
// speedup vs baseline: 1.4682x; 1.0107x over previous
#include <cuda_runtime.h>
#include <cuda_bf16.h>
#include <cuda_fp16.h>
#include <math.h>
#include <stdint.h>

// ---------------- problem constants ----------------
#define NN 10000
#define DD 256
#define EE 320000
#define MAXNORM 0.996f
#define MINNORM 1e-15f
#define ATANH_CLIP (1.0f - 1e-7f)

#define GB 79
#define NNP (GB * 128)    // 10112 padded rows

// ---------------- scratch ----------------
__device__ float g_mx [NN * DD];
__device__ __half g_xth[NN * DD];
__device__ float g_xn[NN];
__device__ float g_bias[DD];
__device__ float g_biasy2;
__device__ __nv_bfloat16 g_ah[NNP * DD];
__device__ __nv_bfloat16 g_al[NNP * DD];
__device__ __nv_bfloat16 g_wh[2 * DD * DD];
__device__ __nv_bfloat16 g_wl[2 * DD * DD];
// CSR-by-dst
__device__ int   g_cnt[NN];
__device__ int   g_off[NN + 1];
__device__ int   g_pos[NN];
__device__ int2  g_csr_pair[EE];   // (src, w-bits)

// ---------------- numerics ----------------
__device__ __forceinline__ float tanh_acc(float x) {
    float a = fabsf(x);
    if (a > 15.f) return copysignf(1.f, x);
    float s = expm1f(2.f * a);
    float r = s / (s + 2.f);
    return copysignf(r, x);
}
__device__ __forceinline__ float atanh_clip(float r) {
    float a = fminf(r, ATANH_CLIP);
    return 0.5f * log1pf(2.f * a / (1.f - a));
}

// ---------------- helpers ----------------
__device__ __forceinline__ float d4(float4 v)  { return v.x*v.x + v.y*v.y + v.z*v.z + v.w*v.w; }
__device__ __forceinline__ float dd4(float4 a, float4 b) { return a.x*b.x + a.y*b.y + a.z*b.z + a.w*b.w; }
__device__ __forceinline__ float4 s4(float4 v, float s) { return make_float4(v.x*s, v.y*s, v.z*s, v.w*s); }
__device__ __forceinline__ float wredsum(float v) {
    #pragma unroll
    for (int o = 16; o; o >>= 1) v += __shfl_xor_sync(0xffffffffu, v, o);
    return v;
}
__device__ __forceinline__ float rownorm(float4 a0, float4 a1) {
    return fmaxf(sqrtf(wredsum(d4(a0) + d4(a1))), MINNORM);
}

// ---------------- bf16 split helpers ----------------
__device__ __forceinline__ uint4 pack8(const unsigned short* u) {
    uint4 r;
    r.x = (uint32_t)u[0] | ((uint32_t)u[1] << 16);
    r.y = (uint32_t)u[2] | ((uint32_t)u[3] << 16);
    r.z = (uint32_t)u[4] | ((uint32_t)u[5] << 16);
    r.w = (uint32_t)u[6] | ((uint32_t)u[7] << 16);
    return r;
}
// write bf16 hi/lo split of 8 floats (cols lane*8..+7) for row
__device__ __forceinline__ void write_split(int row, int lane, const float* f) {
    unsigned short hs[8], ls[8];
    #pragma unroll
    for (int j = 0; j < 8; j++) {
        __nv_bfloat16 hb = __float2bfloat16(f[j]);
        float hf = __bfloat162float(hb);
        __nv_bfloat16 lb = __float2bfloat16(f[j] - hf);
        hs[j] = __bfloat16_as_ushort(hb);
        ls[j] = __bfloat16_as_ushort(lb);
    }
    size_t o = (size_t)row * 256 + lane * 8;
    *(uint4*)(g_ah + o) = pack8(hs);
    *(uint4*)(g_al + o) = pack8(ls);
}

// ---------------- stage A: h = proj(expmap0(x)) -> split + norm ----------
__global__ void k_init(const float* __restrict__ x) {
    int gi = blockIdx.x * blockDim.x + threadIdx.x;
    if (gi < NN) g_cnt[gi] = 0;
    if (gi < (NNP - NN) * 32) {           // zero pad rows of g_ah/g_al
        uint4 z = make_uint4(0, 0, 0, 0);
        ((uint4*)(g_ah + (size_t)NN * 256))[gi] = z;
        ((uint4*)(g_al + (size_t)NN * 256))[gi] = z;
    }
    int lane = threadIdx.x & 31;
    int row = blockIdx.x * 8 + (threadIdx.x >> 5);
    if (row >= NN) return;
    const float4* xp = (const float4*)(x + (size_t)row * 256);
    float4 v0 = xp[2 * lane], v1 = xp[2 * lane + 1];   // cols lane*8..+7
    float n = rownorm(v0, v1);
    float s = tanh_acc(n) / n;
    float4 e0 = s4(v0, s), e1 = s4(v1, s);
    float n2 = rownorm(e0, e1);
    if (n2 > MAXNORM) { float f = MAXNORM / n2; e0 = s4(e0, f); e1 = s4(e1, f); }
    if (lane == 0) g_xn[row] = fminf(n2, MAXNORM);
    float f[8] = {e0.x, e0.y, e0.z, e0.w, e1.x, e1.y, e1.z, e1.w};
    write_split(row, lane, f);
}

// ---------------- CSR build (4 edges/thread for MLP) ----------------
__global__ void k_hist(const int* __restrict__ edst) {
    int base = blockIdx.x * 1024 + threadIdx.x;
    int d0 = (base           < EE) ? __ldg(&edst[base])        : -1;
    int d1 = (base + 256     < EE) ? __ldg(&edst[base + 256])  : -1;
    int d2 = (base + 512     < EE) ? __ldg(&edst[base + 512])  : -1;
    int d3 = (base + 768     < EE) ? __ldg(&edst[base + 768])  : -1;
    if (d0 >= 0) atomicAdd(&g_cnt[d0], 1);
    if (d1 >= 0) atomicAdd(&g_cnt[d1], 1);
    if (d2 >= 0) atomicAdd(&g_cnt[d2], 1);
    if (d3 >= 0) atomicAdd(&g_cnt[d3], 1);
}
__global__ __launch_bounds__(1024) void k_scan() {
    __shared__ int warp_sums[32];
    int tid = threadIdx.x, lane = tid & 31, wid = tid >> 5;
    int base = tid * 10;
    int v[10]; int s = 0;
    #pragma unroll
    for (int j = 0; j < 10; j++) {
        int i = base + j;
        v[j] = (i < NN) ? g_cnt[i] : 0;
        s += v[j];
    }
    int x = s;
    #pragma unroll
    for (int o = 1; o < 32; o <<= 1) {
        int y = __shfl_up_sync(0xffffffffu, x, o);
        if (lane >= o) x += y;
    }
    if (lane == 31) warp_sums[wid] = x;
    __syncthreads();
    if (wid == 0) {
        int t = warp_sums[lane];
        #pragma unroll
        for (int o = 1; o < 32; o <<= 1) {
            int y = __shfl_up_sync(0xffffffffu, t, o);
            if (lane >= o) t += y;
        }
        warp_sums[lane] = t;
    }
    __syncthreads();
    int prefix = ((wid > 0) ? warp_sums[wid - 1] : 0) + (x - s);
    #pragma unroll
    for (int j = 0; j < 10; j++) {
        int i = base + j;
        if (i < NN) { g_off[i] = prefix; g_pos[i] = prefix; }
        prefix += v[j];
    }
    if (tid == 1023) g_off[NN] = prefix;
}
__global__ void k_fill(const int* __restrict__ esrc, const int* __restrict__ edst,
                       const float* __restrict__ ew) {
    int base = blockIdx.x * 1024 + threadIdx.x;
    int i0 = base, i1 = base + 256, i2 = base + 512, i3 = base + 768;
    int d0 = (i0 < EE) ? __ldg(&edst[i0]) : -1;
    int d1 = (i1 < EE) ? __ldg(&edst[i1]) : -1;
    int d2 = (i2 < EE) ? __ldg(&edst[i2]) : -1;
    int d3 = (i3 < EE) ? __ldg(&edst[i3]) : -1;
    int s0 = (i0 < EE) ? __ldg(&esrc[i0]) : 0;
    int s1 = (i1 < EE) ? __ldg(&esrc[i1]) : 0;
    int s2 = (i2 < EE) ? __ldg(&esrc[i2]) : 0;
    int s3 = (i3 < EE) ? __ldg(&esrc[i3]) : 0;
    float w0 = (i0 < EE) ? __ldg(&ew[i0]) : 0.f;
    float w1 = (i1 < EE) ? __ldg(&ew[i1]) : 0.f;
    float w2 = (i2 < EE) ? __ldg(&ew[i2]) : 0.f;
    float w3 = (i3 < EE) ? __ldg(&ew[i3]) : 0.f;
    int p0 = (d0 >= 0) ? atomicAdd(&g_pos[d0], 1) : 0;
    int p1 = (d1 >= 0) ? atomicAdd(&g_pos[d1], 1) : 0;
    int p2 = (d2 >= 0) ? atomicAdd(&g_pos[d2], 1) : 0;
    int p3 = (d3 >= 0) ? atomicAdd(&g_pos[d3], 1) : 0;
    if (d0 >= 0) g_csr_pair[p0] = make_int2(s0, __float_as_int(w0));
    if (d1 >= 0) g_csr_pair[p1] = make_int2(s1, __float_as_int(w1));
    if (d2 >= 0) g_csr_pair[p2] = make_int2(s2, __float_as_int(w2));
    if (d3 >= 0) g_csr_pair[p3] = make_int2(s3, __float_as_int(w3));
}

// ---------------- bias ----------------
__global__ void k_bias(const float* __restrict__ b) {
    int lane = threadIdx.x;
    const float4* bp = (const float4*)b;
    float4 v0 = bp[lane], v1 = bp[lane + 32];
    float n = rownorm(v0, v1);
    float s = tanh_acc(n) / n;
    v0 = s4(v0, s); v1 = s4(v1, s);
    float n2 = rownorm(v0, v1);
    if (n2 > MAXNORM) { float f = MAXNORM / n2; v0 = s4(v0, f); v1 = s4(v1, f); }
    float y2 = wredsum(d4(v0) + d4(v1));
    ((float4*)g_bias)[lane] = v0;
    ((float4*)g_bias)[lane + 32] = v1;
    if (lane == 0) g_biasy2 = y2;
}

// ---------------- convert W1,W2 -> bf16 hi/lo (once) ----------------
__global__ void k_convW(const float* __restrict__ W1, const float* __restrict__ W2) {
    int w = threadIdx.x >> 5, lane = threadIdx.x & 31;
    int row = blockIdx.x * 8 + w;         // 0..511
    if (row >= 512) return;
    const float* src = (row < 256) ? (W1 + (size_t)row * 256) : (W2 + (size_t)(row - 256) * 256);
    int layer = row >> 8;
    int lrow = row & 255;
    const float4* sp = (const float4*)src;
    float4 a = sp[lane * 2], b = sp[lane * 2 + 1];
    float f[8] = {a.x, a.y, a.z, a.w, b.x, b.y, b.z, b.w};
    unsigned short hs[8], ls[8];
    #pragma unroll
    for (int j = 0; j < 8; j++) {
        __nv_bfloat16 hb = __float2bfloat16(f[j]);
        float hf = __bfloat162float(hb);
        __nv_bfloat16 lb = __float2bfloat16(f[j] - hf);
        hs[j] = __bfloat16_as_ushort(hb);
        ls[j] = __bfloat16_as_ushort(lb);
    }
    size_t o = (size_t)layer * 65536 + (size_t)lrow * 256 + lane * 8;
    *(uint4*)(g_wh + o) = pack8(hs);
    *(uint4*)(g_wl + o) = pack8(ls);
}

// ---------------- HMMA bf16-split GEMM: g_mx = h @ W^T ----------------
__device__ __forceinline__ void ldsm4(uint32_t addr, uint32_t* r) {
    asm volatile("ldmatrix.sync.aligned.m8n8.x4.shared.b16 {%0,%1,%2,%3}, [%4];"
                 : "=r"(r[0]), "=r"(r[1]), "=r"(r[2]), "=r"(r[3]) : "r"(addr));
}
__device__ __forceinline__ void mma16816(float* c, const uint32_t* a, uint32_t b0, uint32_t b1) {
    asm volatile(
        "mma.sync.aligned.m16n8k16.row.col.f32.bf16.bf16.f32 "
        "{%0,%1,%2,%3}, {%4,%5,%6,%7}, {%8,%9}, {%0,%1,%2,%3};"
        : "+f"(c[0]), "+f"(c[1]), "+f"(c[2]), "+f"(c[3])
        : "r"(a[0]), "r"(a[1]), "r"(a[2]), "r"(a[3]), "r"(b0), "r"(b1));
}

#define HS_AH 0
#define HS_AL 16384
#define HS_BH 32768
#define HS_BL 49152
#define HS_TOTAL 65536

__global__ __launch_bounds__(256, 1) void k_hmma(int layer) {
    extern __shared__ __align__(1024) char smem[];
    uint32_t sb;
    asm("{ .reg .u64 t; cvta.to.shared.u64 t, %1; cvt.u32.u64 %0, t; }" : "=r"(sb) : "l"(smem));
    int tid = threadIdx.x, lane = tid & 31, wid = tid >> 5;
    int wm = wid & 3, wn = wid >> 2;
    int m0 = blockIdx.x * 128, n0 = blockIdx.y * 128;
    const __nv_bfloat16* wh = g_wh + (size_t)layer * 65536;
    const __nv_bfloat16* wl = g_wl + (size_t)layer * 65536;

    float acc[2][8][4];
    #pragma unroll
    for (int mt = 0; mt < 2; mt++)
        #pragma unroll
        for (int nt = 0; nt < 8; nt++)
            #pragma unroll
            for (int q = 0; q < 4; q++) acc[mt][nt][q] = 0.f;

    for (int ch = 0; ch < 4; ch++) {
        int k0 = ch * 64;
        #pragma unroll
        for (int i = 0; i < 4; i++) {
            int idx = tid + 256 * i;            // 0..1023
            int r = idx >> 3, c = idx & 7;
            uint32_t dst = (uint32_t)(r * 8 + (c ^ (r & 7))) * 16;
            *(uint4*)(smem + HS_AH + dst) = *(const uint4*)(g_ah + (size_t)(m0 + r) * 256 + k0 + c * 8);
            *(uint4*)(smem + HS_AL + dst) = *(const uint4*)(g_al + (size_t)(m0 + r) * 256 + k0 + c * 8);
            *(uint4*)(smem + HS_BH + dst) = *(const uint4*)(wh + (size_t)(n0 + r) * 256 + k0 + c * 8);
            *(uint4*)(smem + HS_BL + dst) = *(const uint4*)(wl + (size_t)(n0 + r) * 256 + k0 + c * 8);
        }
        __syncthreads();
        #pragma unroll
        for (int kk = 0; kk < 4; kk++) {
            uint32_t ah[2][4], al[2][4];
            #pragma unroll
            for (int mt = 0; mt < 2; mt++) {
                int row = wm * 32 + mt * 16 + (lane & 15);
                int ck = kk * 2 + (lane >> 4);
                uint32_t off = (uint32_t)(row * 8 + (ck ^ (row & 7))) * 16;
                ldsm4(sb + HS_AH + off, ah[mt]);
                ldsm4(sb + HS_AL + off, al[mt]);
            }
            #pragma unroll
            for (int ng = 0; ng < 4; ng++) {
                int row = wn * 64 + ng * 16 + ((lane >> 4) << 3) + (lane & 7);
                int ck = kk * 2 + ((lane >> 3) & 1);
                uint32_t off = (uint32_t)(row * 8 + (ck ^ (row & 7))) * 16;
                uint32_t bh[4], bl[4];
                ldsm4(sb + HS_BH + off, bh);
                ldsm4(sb + HS_BL + off, bl);
                #pragma unroll
                for (int mt = 0; mt < 2; mt++) {
                    mma16816(acc[mt][ng*2+0], ah[mt], bh[0], bh[1]);
                    mma16816(acc[mt][ng*2+0], ah[mt], bl[0], bl[1]);
                    mma16816(acc[mt][ng*2+0], al[mt], bh[0], bh[1]);
                    mma16816(acc[mt][ng*2+1], ah[mt], bh[2], bh[3]);
                    mma16816(acc[mt][ng*2+1], ah[mt], bl[2], bl[3]);
                    mma16816(acc[mt][ng*2+1], al[mt], bh[2], bh[3]);
                }
            }
        }
        __syncthreads();
    }

    #pragma unroll
    for (int mt = 0; mt < 2; mt++) {
        int mrow0 = m0 + wm * 32 + mt * 16 + (lane >> 2);
        #pragma unroll
        for (int nt = 0; nt < 8; nt++) {
            int col = n0 + wn * 64 + nt * 8 + 2 * (lane & 3);
            if (mrow0 < NN)
                *(float2*)(g_mx + (size_t)mrow0 * 256 + col) = make_float2(acc[mt][nt][0], acc[mt][nt][1]);
            if (mrow0 + 8 < NN)
                *(float2*)(g_mx + (size_t)(mrow0 + 8) * 256 + col) = make_float2(acc[mt][nt][2], acc[mt][nt][3]);
        }
    }
}

// ---------------- fused HypLinear tail + logmap0 → g_xth (fp16) ----------
__global__ void k_pre() {
    int lane = threadIdx.x & 31;
    int row = blockIdx.x * 8 + (threadIdx.x >> 5);
    if (row >= NN) return;
    const float4* mp = (const float4*)(g_mx + (size_t)row * 256);
    float4 m0 = mp[2*lane], m1 = mp[2*lane+1];

    float xn  = g_xn[row];
    float mn2 = wredsum(d4(m0) + d4(m1));
    bool  zero = (mn2 == 0.f);
    float mxn = fmaxf(sqrtf(mn2), MINNORM);
    float arg = mxn / xn * atanh_clip(xn);
    float sc  = tanh_acc(arg) / mxn;
    if (zero) sc = 0.f;
    float4 r0 = s4(m0, sc), r1 = s4(m1, sc);
    float rn = rownorm(r0, r1);
    if (rn > MAXNORM) { float f = MAXNORM / rn; r0 = s4(r0, f); r1 = s4(r1, f); }

    const float4* gb = (const float4*)g_bias;
    float4 b0 = gb[2*lane], b1 = gb[2*lane+1];
    float x2 = wredsum(d4(r0) + d4(r1));
    float xy = wredsum(dd4(r0, b0) + dd4(r1, b1));
    float y2 = g_biasy2;
    float ca = 1.f + 2.f * xy + y2;
    float cb = 1.f - x2;
    float den = fmaxf(1.f + 2.f * xy + x2 * y2, MINNORM);
    float4 q0, q1;
    q0.x = (ca*r0.x + cb*b0.x)/den; q0.y = (ca*r0.y + cb*b0.y)/den;
    q0.z = (ca*r0.z + cb*b0.z)/den; q0.w = (ca*r0.w + cb*b0.w)/den;
    q1.x = (ca*r1.x + cb*b1.x)/den; q1.y = (ca*r1.y + cb*b1.y)/den;
    q1.z = (ca*r1.z + cb*b1.z)/den; q1.w = (ca*r1.w + cb*b1.w)/den;
    float qn = rownorm(q0, q1);
    if (qn > MAXNORM) { float f = MAXNORM / qn; q0 = s4(q0, f); q1 = s4(q1, f); }

    float pn = rownorm(q0, q1);
    float ls = atanh_clip(pn) / pn;
    q0 = s4(q0, ls); q1 = s4(q1, ls);

    __half2 hx = __float22half2_rn(make_float2(q0.x, q0.y));
    __half2 hy = __float22half2_rn(make_float2(q0.z, q0.w));
    __half2 hz = __float22half2_rn(make_float2(q1.x, q1.y));
    __half2 hw = __float22half2_rn(make_float2(q1.z, q1.w));
    uint4 pk;
    pk.x = *(uint32_t*)&hx; pk.y = *(uint32_t*)&hy;
    pk.z = *(uint32_t*)&hz; pk.w = *(uint32_t*)&hw;
    *(uint4*)(g_xth + (size_t)row * 256 + lane * 8) = pk;
}

// ---------------- fused CSR aggregation (fp16 gather) + HypAgg/HypAct ----
__global__ __launch_bounds__(256) void k_aggpost(float* __restrict__ out, int write_out) {
    int lane = threadIdx.x & 31;
    int row = blockIdx.x * 8 + (threadIdx.x >> 5);
    if (row >= NN) return;
    int beg = g_off[row], end = g_off[row + 1];

    float acc[8];
    #pragma unroll
    for (int j = 0; j < 8; j++) acc[j] = 0.f;

    for (int c = beg; c < end; c += 32) {
        int n = end - c; if (n > 32) n = 32;
        int2 pv = make_int2(0, 0);
        if (lane < n) pv = __ldg(&g_csr_pair[c + lane]);
        int j = 0;
        for (; j + 1 < n; j += 2) {
            int   s0 = __shfl_sync(0xffffffffu, pv.x, j);
            int   s1 = __shfl_sync(0xffffffffu, pv.x, j + 1);
            float w0 = __int_as_float(__shfl_sync(0xffffffffu, pv.y, j));
            float w1 = __int_as_float(__shfl_sync(0xffffffffu, pv.y, j + 1));
            uint4 u = __ldg((const uint4*)(g_xth + (size_t)s0 * 256) + lane);
            uint4 t = __ldg((const uint4*)(g_xth + (size_t)s1 * 256) + lane);
            const __half2* uh = (const __half2*)&u;
            const __half2* th = (const __half2*)&t;
            #pragma unroll
            for (int q = 0; q < 4; q++) {
                float2 fu = __half22float2(uh[q]);
                float2 ft = __half22float2(th[q]);
                acc[q*2+0] = fmaf(fu.x, w0, acc[q*2+0]);
                acc[q*2+1] = fmaf(fu.y, w0, acc[q*2+1]);
                acc[q*2+0] = fmaf(ft.x, w1, acc[q*2+0]);
                acc[q*2+1] = fmaf(ft.y, w1, acc[q*2+1]);
            }
        }
        if (j < n) {
            int   s0 = __shfl_sync(0xffffffffu, pv.x, j);
            float w0 = __int_as_float(__shfl_sync(0xffffffffu, pv.y, j));
            uint4 u = __ldg((const uint4*)(g_xth + (size_t)s0 * 256) + lane);
            const __half2* uh = (const __half2*)&u;
            #pragma unroll
            for (int q = 0; q < 4; q++) {
                float2 fu = __half22float2(uh[q]);
                acc[q*2+0] = fmaf(fu.x, w0, acc[q*2+0]);
                acc[q*2+1] = fmaf(fu.y, w0, acc[q*2+1]);
            }
        }
    }

    float4 a0 = make_float4(acc[0], acc[1], acc[2], acc[3]);
    float4 a1 = make_float4(acc[4], acc[5], acc[6], acc[7]);

    float n1 = rownorm(a0, a1);
    float s = tanh_acc(n1) / n1;
    float4 e0 = s4(a0, s), e1 = s4(a1, s);
    float n2 = rownorm(e0, e1);
    if (n2 > MAXNORM) { float f = MAXNORM / n2; e0 = s4(e0, f); e1 = s4(e1, f); }
    float pn = rownorm(e0, e1);
    float ls = atanh_clip(pn) / pn;
    float4 u0, u1;
    u0.x = fmaxf(e0.x * ls, 0.f); u0.y = fmaxf(e0.y * ls, 0.f);
    u0.z = fmaxf(e0.z * ls, 0.f); u0.w = fmaxf(e0.w * ls, 0.f);
    u1.x = fmaxf(e1.x * ls, 0.f); u1.y = fmaxf(e1.y * ls, 0.f);
    u1.z = fmaxf(e1.z * ls, 0.f); u1.w = fmaxf(e1.w * ls, 0.f);
    float un = rownorm(u0, u1);
    float s2 = tanh_acc(un) / un;
    float4 o0 = s4(u0, s2), o1 = s4(u1, s2);
    float n3 = rownorm(o0, o1);
    if (n3 > MAXNORM) { float f = MAXNORM / n3; o0 = s4(o0, f); o1 = s4(o1, f); }

    if (write_out) {
        float4* dst = (float4*)(out + (size_t)row * 256);
        dst[2*lane] = o0; dst[2*lane+1] = o1;
    } else {
        if (lane == 0) g_xn[row] = fminf(n3, MAXNORM);
        float f[8] = {o0.x, o0.y, o0.z, o0.w, o1.x, o1.y, o1.z, o1.w};
        write_split(row, lane, f);
    }
}

// ---------------- launch ----------------
extern "C" void kernel_launch(void* const* d_in, const int* in_sizes, int n_in,
                              void* d_out, int out_size) {
    const float* x    = (const float*)d_in[0];
    const float* W1   = (const float*)d_in[1];
    const float* b1   = (const float*)d_in[2];
    const float* W2   = (const float*)d_in[3];
    const float* b2   = (const float*)d_in[4];
    const float* ew   = (const float*)d_in[5];
    const int*   esrc = (const int*)d_in[6];
    const int*   edst = (const int*)d_in[7];
    float* out = (float*)d_out;
    (void)in_sizes; (void)n_in; (void)out_size;

    const int rowBlocks = (NN + 7) / 8;
    const int e4Blocks  = (EE + 1023) / 1024;
    dim3 hmmaGrid(GB, 2);

    cudaFuncSetAttribute(k_hmma, cudaFuncAttributeMaxDynamicSharedMemorySize, HS_TOTAL);

    k_init<<<rowBlocks, 256>>>(x);
    k_hist<<<e4Blocks, 256>>>(edst);
    k_scan<<<1, 1024>>>();
    k_fill<<<e4Blocks, 256>>>(esrc, edst, ew);
    k_convW<<<64, 256>>>(W1, W2);

    // layer 1
    k_bias<<<1, 32>>>(b1);
    k_hmma<<<hmmaGrid, 256, HS_TOTAL>>>(0);
    k_pre<<<rowBlocks, 256>>>();
    k_aggpost<<<rowBlocks, 256>>>(out, 0);

    // layer 2
    k_bias<<<1, 32>>>(b2);
    k_hmma<<<hmmaGrid, 256, HS_TOTAL>>>(1);
    k_pre<<<rowBlocks, 256>>>();
    k_aggpost<<<rowBlocks, 256>>>(out, 1);
}

// round 16
// speedup vs baseline: 1.5109x; 1.0291x over previous
#include <cuda_runtime.h>
#include <cuda_bf16.h>
#include <cuda_fp16.h>
#include <math.h>
#include <stdint.h>

// ---------------- problem constants ----------------
#define NN 10000
#define DD 256
#define EE 320000
#define MAXNORM 0.996f
#define MINNORM 1e-15f
#define ATANH_CLIP (1.0f - 1e-7f)

#define GB 79
#define NNP (GB * 128)    // 10112 padded rows

// ---------------- scratch ----------------
__device__ float g_mx [NN * DD];
__device__ __half g_xth[NN * DD];
__device__ float g_xn[NN];
__device__ float g_bias[2 * DD];
__device__ float g_biasy2v[2];
__device__ __nv_bfloat16 g_ah[NNP * DD];
__device__ __nv_bfloat16 g_al[NNP * DD];
__device__ __nv_bfloat16 g_wh[2 * DD * DD];
__device__ __nv_bfloat16 g_wl[2 * DD * DD];
// CSR-by-dst
__device__ int   g_cnt[NN];
__device__ int   g_off[NN + 1];
__device__ int   g_pos[NN];
__device__ int2  g_csr_pair[EE];   // (src, w-bits)

// ---------------- numerics ----------------
__device__ __forceinline__ float tanh_acc(float x) {
    float a = fabsf(x);
    if (a > 15.f) return copysignf(1.f, x);
    float s = expm1f(2.f * a);
    float r = s / (s + 2.f);
    return copysignf(r, x);
}
__device__ __forceinline__ float atanh_clip(float r) {
    float a = fminf(r, ATANH_CLIP);
    return 0.5f * log1pf(2.f * a / (1.f - a));
}

// ---------------- helpers ----------------
__device__ __forceinline__ float d4(float4 v)  { return v.x*v.x + v.y*v.y + v.z*v.z + v.w*v.w; }
__device__ __forceinline__ float dd4(float4 a, float4 b) { return a.x*b.x + a.y*b.y + a.z*b.z + a.w*b.w; }
__device__ __forceinline__ float4 s4(float4 v, float s) { return make_float4(v.x*s, v.y*s, v.z*s, v.w*s); }
__device__ __forceinline__ float wredsum(float v) {
    #pragma unroll
    for (int o = 16; o; o >>= 1) v += __shfl_xor_sync(0xffffffffu, v, o);
    return v;
}
__device__ __forceinline__ float rownorm(float4 a0, float4 a1) {
    return fmaxf(sqrtf(wredsum(d4(a0) + d4(a1))), MINNORM);
}

// ---------------- bf16 split helpers ----------------
__device__ __forceinline__ uint4 pack8(const unsigned short* u) {
    uint4 r;
    r.x = (uint32_t)u[0] | ((uint32_t)u[1] << 16);
    r.y = (uint32_t)u[2] | ((uint32_t)u[3] << 16);
    r.z = (uint32_t)u[4] | ((uint32_t)u[5] << 16);
    r.w = (uint32_t)u[6] | ((uint32_t)u[7] << 16);
    return r;
}
__device__ __forceinline__ void write_split(int row, int lane, const float* f) {
    unsigned short hs[8], ls[8];
    #pragma unroll
    for (int j = 0; j < 8; j++) {
        __nv_bfloat16 hb = __float2bfloat16(f[j]);
        float hf = __bfloat162float(hb);
        __nv_bfloat16 lb = __float2bfloat16(f[j] - hf);
        hs[j] = __bfloat16_as_ushort(hb);
        ls[j] = __bfloat16_as_ushort(lb);
    }
    size_t o = (size_t)row * 256 + lane * 8;
    *(uint4*)(g_ah + o) = pack8(hs);
    *(uint4*)(g_al + o) = pack8(ls);
}

// ---------------- stage A: h = proj(expmap0(x)) -> split + norm ----------
__global__ void k_init(const float* __restrict__ x) {
    int gi = blockIdx.x * blockDim.x + threadIdx.x;
    if (gi < NN) g_cnt[gi] = 0;
    if (gi < (NNP - NN) * 32) {           // zero pad rows of g_ah/g_al
        uint4 z = make_uint4(0, 0, 0, 0);
        ((uint4*)(g_ah + (size_t)NN * 256))[gi] = z;
        ((uint4*)(g_al + (size_t)NN * 256))[gi] = z;
    }
    int lane = threadIdx.x & 31;
    int row = blockIdx.x * 8 + (threadIdx.x >> 5);
    if (row >= NN) return;
    const float4* xp = (const float4*)(x + (size_t)row * 256);
    float4 v0 = xp[2 * lane], v1 = xp[2 * lane + 1];
    float n = rownorm(v0, v1);
    float s = tanh_acc(n) / n;
    float4 e0 = s4(v0, s), e1 = s4(v1, s);
    float n2 = rownorm(e0, e1);
    if (n2 > MAXNORM) { float f = MAXNORM / n2; e0 = s4(e0, f); e1 = s4(e1, f); }
    if (lane == 0) g_xn[row] = fminf(n2, MAXNORM);
    float f[8] = {e0.x, e0.y, e0.z, e0.w, e1.x, e1.y, e1.z, e1.w};
    write_split(row, lane, f);
}

// ---------------- CSR build (1 edge/thread; high occupancy) ----------------
__global__ void k_hist(const int* __restrict__ edst) {
    int i = blockIdx.x * blockDim.x + threadIdx.x;
    if (i < EE) atomicAdd(&g_cnt[edst[i]], 1);
}
__global__ __launch_bounds__(1024) void k_scan() {
    __shared__ int warp_sums[32];
    int tid = threadIdx.x, lane = tid & 31, wid = tid >> 5;
    int base = tid * 10;
    int v[10]; int s = 0;
    #pragma unroll
    for (int j = 0; j < 10; j++) {
        int i = base + j;
        v[j] = (i < NN) ? g_cnt[i] : 0;
        s += v[j];
    }
    int x = s;
    #pragma unroll
    for (int o = 1; o < 32; o <<= 1) {
        int y = __shfl_up_sync(0xffffffffu, x, o);
        if (lane >= o) x += y;
    }
    if (lane == 31) warp_sums[wid] = x;
    __syncthreads();
    if (wid == 0) {
        int t = warp_sums[lane];
        #pragma unroll
        for (int o = 1; o < 32; o <<= 1) {
            int y = __shfl_up_sync(0xffffffffu, t, o);
            if (lane >= o) t += y;
        }
        warp_sums[lane] = t;
    }
    __syncthreads();
    int prefix = ((wid > 0) ? warp_sums[wid - 1] : 0) + (x - s);
    #pragma unroll
    for (int j = 0; j < 10; j++) {
        int i = base + j;
        if (i < NN) { g_off[i] = prefix; g_pos[i] = prefix; }
        prefix += v[j];
    }
    if (tid == 1023) g_off[NN] = prefix;
}
__global__ void k_fill(const int* __restrict__ esrc, const int* __restrict__ edst,
                       const float* __restrict__ ew) {
    int i = blockIdx.x * blockDim.x + threadIdx.x;
    if (i < EE) {
        int d = edst[i];
        int p = atomicAdd(&g_pos[d], 1);
        g_csr_pair[p] = make_int2(esrc[i], __float_as_int(ew[i]));
    }
}

// ---------------- both biases at once (2 warps) ----------------
__global__ void k_bias2(const float* __restrict__ b1, const float* __restrict__ b2) {
    int lane = threadIdx.x & 31, w = threadIdx.x >> 5;   // w = layer
    const float* b = (w == 0) ? b1 : b2;
    const float4* bp = (const float4*)b;
    float4 v0 = bp[lane], v1 = bp[lane + 32];
    float n = rownorm(v0, v1);
    float s = tanh_acc(n) / n;
    v0 = s4(v0, s); v1 = s4(v1, s);
    float n2 = rownorm(v0, v1);
    if (n2 > MAXNORM) { float f = MAXNORM / n2; v0 = s4(v0, f); v1 = s4(v1, f); }
    float y2 = wredsum(d4(v0) + d4(v1));
    float4* gb = (float4*)(g_bias + w * 256);
    gb[lane] = v0; gb[lane + 32] = v1;
    if (lane == 0) g_biasy2v[w] = y2;
}

// ---------------- convert W1,W2 -> bf16 hi/lo (once) ----------------
__global__ void k_convW(const float* __restrict__ W1, const float* __restrict__ W2) {
    int w = threadIdx.x >> 5, lane = threadIdx.x & 31;
    int row = blockIdx.x * 8 + w;         // 0..511
    if (row >= 512) return;
    const float* src = (row < 256) ? (W1 + (size_t)row * 256) : (W2 + (size_t)(row - 256) * 256);
    int layer = row >> 8;
    int lrow = row & 255;
    const float4* sp = (const float4*)src;
    float4 a = sp[lane * 2], b = sp[lane * 2 + 1];
    float f[8] = {a.x, a.y, a.z, a.w, b.x, b.y, b.z, b.w};
    unsigned short hs[8], ls[8];
    #pragma unroll
    for (int j = 0; j < 8; j++) {
        __nv_bfloat16 hb = __float2bfloat16(f[j]);
        float hf = __bfloat162float(hb);
        __nv_bfloat16 lb = __float2bfloat16(f[j] - hf);
        hs[j] = __bfloat16_as_ushort(hb);
        ls[j] = __bfloat16_as_ushort(lb);
    }
    size_t o = (size_t)layer * 65536 + (size_t)lrow * 256 + lane * 8;
    *(uint4*)(g_wh + o) = pack8(hs);
    *(uint4*)(g_wl + o) = pack8(ls);
}

// ---------------- HMMA bf16-split GEMM: g_mx = h @ W^T ----------------
__device__ __forceinline__ void ldsm4(uint32_t addr, uint32_t* r) {
    asm volatile("ldmatrix.sync.aligned.m8n8.x4.shared.b16 {%0,%1,%2,%3}, [%4];"
                 : "=r"(r[0]), "=r"(r[1]), "=r"(r[2]), "=r"(r[3]) : "r"(addr));
}
__device__ __forceinline__ void mma16816(float* c, const uint32_t* a, uint32_t b0, uint32_t b1) {
    asm volatile(
        "mma.sync.aligned.m16n8k16.row.col.f32.bf16.bf16.f32 "
        "{%0,%1,%2,%3}, {%4,%5,%6,%7}, {%8,%9}, {%0,%1,%2,%3};"
        : "+f"(c[0]), "+f"(c[1]), "+f"(c[2]), "+f"(c[3])
        : "r"(a[0]), "r"(a[1]), "r"(a[2]), "r"(a[3]), "r"(b0), "r"(b1));
}

#define HS_AH 0
#define HS_AL 16384
#define HS_BH 32768
#define HS_BL 49152
#define HS_TOTAL 65536

__global__ __launch_bounds__(256, 2) void k_hmma(int layer) {
    extern __shared__ __align__(1024) char smem[];
    uint32_t sb;
    asm("{ .reg .u64 t; cvta.to.shared.u64 t, %1; cvt.u32.u64 %0, t; }" : "=r"(sb) : "l"(smem));
    int tid = threadIdx.x, lane = tid & 31, wid = tid >> 5;
    int wm = wid & 3, wn = wid >> 2;
    int m0 = blockIdx.x * 128, n0 = blockIdx.y * 128;
    const __nv_bfloat16* wh = g_wh + (size_t)layer * 65536;
    const __nv_bfloat16* wl = g_wl + (size_t)layer * 65536;

    float acc[2][8][4];
    #pragma unroll
    for (int mt = 0; mt < 2; mt++)
        #pragma unroll
        for (int nt = 0; nt < 8; nt++)
            #pragma unroll
            for (int q = 0; q < 4; q++) acc[mt][nt][q] = 0.f;

    for (int ch = 0; ch < 4; ch++) {
        int k0 = ch * 64;
        #pragma unroll
        for (int i = 0; i < 4; i++) {
            int idx = tid + 256 * i;            // 0..1023
            int r = idx >> 3, c = idx & 7;
            uint32_t dst = (uint32_t)(r * 8 + (c ^ (r & 7))) * 16;
            *(uint4*)(smem + HS_AH + dst) = *(const uint4*)(g_ah + (size_t)(m0 + r) * 256 + k0 + c * 8);
            *(uint4*)(smem + HS_AL + dst) = *(const uint4*)(g_al + (size_t)(m0 + r) * 256 + k0 + c * 8);
            *(uint4*)(smem + HS_BH + dst) = *(const uint4*)(wh + (size_t)(n0 + r) * 256 + k0 + c * 8);
            *(uint4*)(smem + HS_BL + dst) = *(const uint4*)(wl + (size_t)(n0 + r) * 256 + k0 + c * 8);
        }
        __syncthreads();
        #pragma unroll
        for (int kk = 0; kk < 4; kk++) {
            uint32_t ah[2][4], al[2][4];
            #pragma unroll
            for (int mt = 0; mt < 2; mt++) {
                int row = wm * 32 + mt * 16 + (lane & 15);
                int ck = kk * 2 + (lane >> 4);
                uint32_t off = (uint32_t)(row * 8 + (ck ^ (row & 7))) * 16;
                ldsm4(sb + HS_AH + off, ah[mt]);
                ldsm4(sb + HS_AL + off, al[mt]);
            }
            #pragma unroll
            for (int ng = 0; ng < 4; ng++) {
                int row = wn * 64 + ng * 16 + ((lane >> 4) << 3) + (lane & 7);
                int ck = kk * 2 + ((lane >> 3) & 1);
                uint32_t off = (uint32_t)(row * 8 + (ck ^ (row & 7))) * 16;
                uint32_t bh[4], bl[4];
                ldsm4(sb + HS_BH + off, bh);
                ldsm4(sb + HS_BL + off, bl);
                #pragma unroll
                for (int mt = 0; mt < 2; mt++) {
                    mma16816(acc[mt][ng*2+0], ah[mt], bh[0], bh[1]);
                    mma16816(acc[mt][ng*2+0], ah[mt], bl[0], bl[1]);
                    mma16816(acc[mt][ng*2+0], al[mt], bh[0], bh[1]);
                    mma16816(acc[mt][ng*2+1], ah[mt], bh[2], bh[3]);
                    mma16816(acc[mt][ng*2+1], ah[mt], bl[2], bl[3]);
                    mma16816(acc[mt][ng*2+1], al[mt], bh[2], bh[3]);
                }
            }
        }
        __syncthreads();
    }

    #pragma unroll
    for (int mt = 0; mt < 2; mt++) {
        int mrow0 = m0 + wm * 32 + mt * 16 + (lane >> 2);
        #pragma unroll
        for (int nt = 0; nt < 8; nt++) {
            int col = n0 + wn * 64 + nt * 8 + 2 * (lane & 3);
            if (mrow0 < NN)
                *(float2*)(g_mx + (size_t)mrow0 * 256 + col) = make_float2(acc[mt][nt][0], acc[mt][nt][1]);
            if (mrow0 + 8 < NN)
                *(float2*)(g_mx + (size_t)(mrow0 + 8) * 256 + col) = make_float2(acc[mt][nt][2], acc[mt][nt][3]);
        }
    }
}

// ---------------- fused HypLinear tail + logmap0 → g_xth (fp16) ----------
__global__ void k_pre(int layer) {
    int lane = threadIdx.x & 31;
    int row = blockIdx.x * 8 + (threadIdx.x >> 5);
    if (row >= NN) return;
    const float4* mp = (const float4*)(g_mx + (size_t)row * 256);
    float4 m0 = mp[2*lane], m1 = mp[2*lane+1];

    float xn  = g_xn[row];
    float mn2 = wredsum(d4(m0) + d4(m1));
    bool  zero = (mn2 == 0.f);
    float mxn = fmaxf(sqrtf(mn2), MINNORM);
    float arg = mxn / xn * atanh_clip(xn);
    float sc  = tanh_acc(arg) / mxn;
    if (zero) sc = 0.f;
    float4 r0 = s4(m0, sc), r1 = s4(m1, sc);
    float rn = rownorm(r0, r1);
    if (rn > MAXNORM) { float f = MAXNORM / rn; r0 = s4(r0, f); r1 = s4(r1, f); }

    const float4* gb = (const float4*)(g_bias + layer * 256);
    float4 b0 = gb[2*lane], b1 = gb[2*lane+1];
    float x2 = wredsum(d4(r0) + d4(r1));
    float xy = wredsum(dd4(r0, b0) + dd4(r1, b1));
    float y2 = g_biasy2v[layer];
    float ca = 1.f + 2.f * xy + y2;
    float cb = 1.f - x2;
    float den = fmaxf(1.f + 2.f * xy + x2 * y2, MINNORM);
    float4 q0, q1;
    q0.x = (ca*r0.x + cb*b0.x)/den; q0.y = (ca*r0.y + cb*b0.y)/den;
    q0.z = (ca*r0.z + cb*b0.z)/den; q0.w = (ca*r0.w + cb*b0.w)/den;
    q1.x = (ca*r1.x + cb*b1.x)/den; q1.y = (ca*r1.y + cb*b1.y)/den;
    q1.z = (ca*r1.z + cb*b1.z)/den; q1.w = (ca*r1.w + cb*b1.w)/den;
    float qn = rownorm(q0, q1);
    if (qn > MAXNORM) { float f = MAXNORM / qn; q0 = s4(q0, f); q1 = s4(q1, f); }

    float pn = rownorm(q0, q1);
    float ls = atanh_clip(pn) / pn;
    q0 = s4(q0, ls); q1 = s4(q1, ls);

    __half2 hx = __float22half2_rn(make_float2(q0.x, q0.y));
    __half2 hy = __float22half2_rn(make_float2(q0.z, q0.w));
    __half2 hz = __float22half2_rn(make_float2(q1.x, q1.y));
    __half2 hw = __float22half2_rn(make_float2(q1.z, q1.w));
    uint4 pk;
    pk.x = *(uint32_t*)&hx; pk.y = *(uint32_t*)&hy;
    pk.z = *(uint32_t*)&hz; pk.w = *(uint32_t*)&hw;
    *(uint4*)(g_xth + (size_t)row * 256 + lane * 8) = pk;
}

// ---------------- fused CSR aggregation (fp16 gather) + HypAgg/HypAct ----
__global__ __launch_bounds__(256) void k_aggpost(float* __restrict__ out, int write_out) {
    int lane = threadIdx.x & 31;
    int row = blockIdx.x * 8 + (threadIdx.x >> 5);
    if (row >= NN) return;
    int beg = g_off[row], end = g_off[row + 1];

    float acc[8];
    #pragma unroll
    for (int j = 0; j < 8; j++) acc[j] = 0.f;

    for (int c = beg; c < end; c += 32) {
        int n = end - c; if (n > 32) n = 32;
        int2 pv = make_int2(0, 0);
        if (lane < n) pv = __ldg(&g_csr_pair[c + lane]);
        int j = 0;
        for (; j + 1 < n; j += 2) {
            int   s0 = __shfl_sync(0xffffffffu, pv.x, j);
            int   s1 = __shfl_sync(0xffffffffu, pv.x, j + 1);
            float w0 = __int_as_float(__shfl_sync(0xffffffffu, pv.y, j));
            float w1 = __int_as_float(__shfl_sync(0xffffffffu, pv.y, j + 1));
            uint4 u = __ldg((const uint4*)(g_xth + (size_t)s0 * 256) + lane);
            uint4 t = __ldg((const uint4*)(g_xth + (size_t)s1 * 256) + lane);
            const __half2* uh = (const __half2*)&u;
            const __half2* th = (const __half2*)&t;
            #pragma unroll
            for (int q = 0; q < 4; q++) {
                float2 fu = __half22float2(uh[q]);
                float2 ft = __half22float2(th[q]);
                acc[q*2+0] = fmaf(fu.x, w0, acc[q*2+0]);
                acc[q*2+1] = fmaf(fu.y, w0, acc[q*2+1]);
                acc[q*2+0] = fmaf(ft.x, w1, acc[q*2+0]);
                acc[q*2+1] = fmaf(ft.y, w1, acc[q*2+1]);
            }
        }
        if (j < n) {
            int   s0 = __shfl_sync(0xffffffffu, pv.x, j);
            float w0 = __int_as_float(__shfl_sync(0xffffffffu, pv.y, j));
            uint4 u = __ldg((const uint4*)(g_xth + (size_t)s0 * 256) + lane);
            const __half2* uh = (const __half2*)&u;
            #pragma unroll
            for (int q = 0; q < 4; q++) {
                float2 fu = __half22float2(uh[q]);
                acc[q*2+0] = fmaf(fu.x, w0, acc[q*2+0]);
                acc[q*2+1] = fmaf(fu.y, w0, acc[q*2+1]);
            }
        }
    }

    float4 a0 = make_float4(acc[0], acc[1], acc[2], acc[3]);
    float4 a1 = make_float4(acc[4], acc[5], acc[6], acc[7]);

    float n1 = rownorm(a0, a1);
    float s = tanh_acc(n1) / n1;
    float4 e0 = s4(a0, s), e1 = s4(a1, s);
    float n2 = rownorm(e0, e1);
    if (n2 > MAXNORM) { float f = MAXNORM / n2; e0 = s4(e0, f); e1 = s4(e1, f); }
    float pn = rownorm(e0, e1);
    float ls = atanh_clip(pn) / pn;
    float4 u0, u1;
    u0.x = fmaxf(e0.x * ls, 0.f); u0.y = fmaxf(e0.y * ls, 0.f);
    u0.z = fmaxf(e0.z * ls, 0.f); u0.w = fmaxf(e0.w * ls, 0.f);
    u1.x = fmaxf(e1.x * ls, 0.f); u1.y = fmaxf(e1.y * ls, 0.f);
    u1.z = fmaxf(e1.z * ls, 0.f); u1.w = fmaxf(e1.w * ls, 0.f);
    float un = rownorm(u0, u1);
    float s2 = tanh_acc(un) / un;
    float4 o0 = s4(u0, s2), o1 = s4(u1, s2);
    float n3 = rownorm(o0, o1);
    if (n3 > MAXNORM) { float f = MAXNORM / n3; o0 = s4(o0, f); o1 = s4(o1, f); }

    if (write_out) {
        float4* dst = (float4*)(out + (size_t)row * 256);
        dst[2*lane] = o0; dst[2*lane+1] = o1;
    } else {
        if (lane == 0) g_xn[row] = fminf(n3, MAXNORM);
        float f[8] = {o0.x, o0.y, o0.z, o0.w, o1.x, o1.y, o1.z, o1.w};
        write_split(row, lane, f);
    }
}

// ---------------- launch ----------------
extern "C" void kernel_launch(void* const* d_in, const int* in_sizes, int n_in,
                              void* d_out, int out_size) {
    const float* x    = (const float*)d_in[0];
    const float* W1   = (const float*)d_in[1];
    const float* b1   = (const float*)d_in[2];
    const float* W2   = (const float*)d_in[3];
    const float* b2   = (const float*)d_in[4];
    const float* ew   = (const float*)d_in[5];
    const int*   esrc = (const int*)d_in[6];
    const int*   edst = (const int*)d_in[7];
    float* out = (float*)d_out;
    (void)in_sizes; (void)n_in; (void)out_size;

    const int rowBlocks = (NN + 7) / 8;
    const int eBlocks   = (EE + 255) / 256;
    dim3 hmmaGrid(GB, 2);

    cudaFuncSetAttribute(k_hmma, cudaFuncAttributeMaxDynamicSharedMemorySize, HS_TOTAL);

    k_init<<<rowBlocks, 256>>>(x);
    k_hist<<<eBlocks, 256>>>(edst);
    k_scan<<<1, 1024>>>();
    k_fill<<<eBlocks, 256>>>(esrc, edst, ew);
    k_convW<<<64, 256>>>(W1, W2);
    k_bias2<<<1, 64>>>(b1, b2);

    // layer 1
    k_hmma<<<hmmaGrid, 256, HS_TOTAL>>>(0);
    k_pre<<<rowBlocks, 256>>>(0);
    k_aggpost<<<rowBlocks, 256>>>(out, 0);

    // layer 2
    k_hmma<<<hmmaGrid, 256, HS_TOTAL>>>(1);
    k_pre<<<rowBlocks, 256>>>(1);
    k_aggpost<<<rowBlocks, 256>>>(out, 1);
}

// round 17
// speedup vs baseline: 1.6001x; 1.0590x over previous
#include <cuda_runtime.h>
#include <cuda_bf16.h>
#include <cuda_fp16.h>
#include <math.h>
#include <stdint.h>

// ---------------- problem constants ----------------
#define NN 10000
#define DD 256
#define EE 320000
#define MAXNORM 0.996f
#define MINNORM 1e-15f
#define ATANH_CLIP (1.0f - 1e-7f)

#define GBX 158
#define NNP (GBX * 64)    // 10112 padded rows

// ---------------- scratch ----------------
__device__ __half g_xth[NN * DD];
__device__ float g_xn[NN];
__device__ float g_bias[2 * DD];
__device__ float g_biasy2v[2];
__device__ __nv_bfloat16 g_ah[NNP * DD];
__device__ __nv_bfloat16 g_al[NNP * DD];
__device__ __nv_bfloat16 g_wh[2 * DD * DD];
__device__ __nv_bfloat16 g_wl[2 * DD * DD];
// CSR-by-dst
__device__ int   g_cnt[NN];
__device__ int   g_off[NN + 1];
__device__ int   g_pos[NN];
__device__ int2  g_csr_pair[EE];   // (src, w-bits)

// ---------------- numerics ----------------
__device__ __forceinline__ float tanh_acc(float x) {
    float a = fabsf(x);
    if (a > 15.f) return copysignf(1.f, x);
    float s = expm1f(2.f * a);
    float r = s / (s + 2.f);
    return copysignf(r, x);
}
__device__ __forceinline__ float atanh_clip(float r) {
    float a = fminf(r, ATANH_CLIP);
    return 0.5f * log1pf(2.f * a / (1.f - a));
}

// ---------------- helpers ----------------
__device__ __forceinline__ float d4(float4 v)  { return v.x*v.x + v.y*v.y + v.z*v.z + v.w*v.w; }
__device__ __forceinline__ float4 s4(float4 v, float s) { return make_float4(v.x*s, v.y*s, v.z*s, v.w*s); }
__device__ __forceinline__ float wredsum(float v) {
    #pragma unroll
    for (int o = 16; o; o >>= 1) v += __shfl_xor_sync(0xffffffffu, v, o);
    return v;
}
__device__ __forceinline__ float rownorm(float4 a0, float4 a1) {
    return fmaxf(sqrtf(wredsum(d4(a0) + d4(a1))), MINNORM);
}

// ---------------- bf16 split helpers ----------------
__device__ __forceinline__ uint4 pack8(const unsigned short* u) {
    uint4 r;
    r.x = (uint32_t)u[0] | ((uint32_t)u[1] << 16);
    r.y = (uint32_t)u[2] | ((uint32_t)u[3] << 16);
    r.z = (uint32_t)u[4] | ((uint32_t)u[5] << 16);
    r.w = (uint32_t)u[6] | ((uint32_t)u[7] << 16);
    return r;
}
__device__ __forceinline__ void write_split(int row, int lane, const float* f) {
    unsigned short hs[8], ls[8];
    #pragma unroll
    for (int j = 0; j < 8; j++) {
        __nv_bfloat16 hb = __float2bfloat16(f[j]);
        float hf = __bfloat162float(hb);
        __nv_bfloat16 lb = __float2bfloat16(f[j] - hf);
        hs[j] = __bfloat16_as_ushort(hb);
        ls[j] = __bfloat16_as_ushort(lb);
    }
    size_t o = (size_t)row * 256 + lane * 8;
    *(uint4*)(g_ah + o) = pack8(hs);
    *(uint4*)(g_al + o) = pack8(ls);
}

// ---------------- convert W1,W2 -> bf16 hi/lo (once); zero g_cnt ----------
__global__ void k_convW(const float* __restrict__ W1, const float* __restrict__ W2) {
    int gi = blockIdx.x * blockDim.x + threadIdx.x;
    if (gi < NN) g_cnt[gi] = 0;
    int w = threadIdx.x >> 5, lane = threadIdx.x & 31;
    int row = blockIdx.x * 8 + w;         // 0..511
    if (row >= 512) return;
    const float* src = (row < 256) ? (W1 + (size_t)row * 256) : (W2 + (size_t)(row - 256) * 256);
    int layer = row >> 8;
    int lrow = row & 255;
    const float4* sp = (const float4*)src;
    float4 a = sp[lane * 2], b = sp[lane * 2 + 1];
    float f[8] = {a.x, a.y, a.z, a.w, b.x, b.y, b.z, b.w};
    unsigned short hs[8], ls[8];
    #pragma unroll
    for (int j = 0; j < 8; j++) {
        __nv_bfloat16 hb = __float2bfloat16(f[j]);
        float hf = __bfloat162float(hb);
        __nv_bfloat16 lb = __float2bfloat16(f[j] - hf);
        hs[j] = __bfloat16_as_ushort(hb);
        ls[j] = __bfloat16_as_ushort(lb);
    }
    size_t o = (size_t)layer * 65536 + (size_t)lrow * 256 + lane * 8;
    *(uint4*)(g_wh + o) = pack8(hs);
    *(uint4*)(g_wl + o) = pack8(ls);
}

// ---------------- stage A: h = proj(expmap0(x)) -> split + norm + hist ---
// grid is exactly EE = 320000 threads: one edge histogram add per thread.
__global__ void k_init(const float* __restrict__ x, const int* __restrict__ edst) {
    int gi = blockIdx.x * blockDim.x + threadIdx.x;
    atomicAdd(&g_cnt[edst[gi]], 1);       // gi < EE always (1250*256 == EE)
    if (gi < (NNP - NN) * 32) {           // zero pad rows of g_ah/g_al
        uint4 z = make_uint4(0, 0, 0, 0);
        ((uint4*)(g_ah + (size_t)NN * 256))[gi] = z;
        ((uint4*)(g_al + (size_t)NN * 256))[gi] = z;
    }
    int lane = threadIdx.x & 31;
    int row = blockIdx.x * 8 + (threadIdx.x >> 5);
    if (row >= NN) return;
    const float4* xp = (const float4*)(x + (size_t)row * 256);
    float4 v0 = xp[2 * lane], v1 = xp[2 * lane + 1];
    float n = rownorm(v0, v1);
    float s = tanh_acc(n) / n;
    float4 e0 = s4(v0, s), e1 = s4(v1, s);
    float n2 = rownorm(e0, e1);
    if (n2 > MAXNORM) { float f = MAXNORM / n2; e0 = s4(e0, f); e1 = s4(e1, f); }
    if (lane == 0) g_xn[row] = fminf(n2, MAXNORM);
    float f[8] = {e0.x, e0.y, e0.z, e0.w, e1.x, e1.y, e1.z, e1.w};
    write_split(row, lane, f);
}

// ---------------- CSR scan/fill ----------------
__global__ __launch_bounds__(1024) void k_scan() {
    __shared__ int warp_sums[32];
    int tid = threadIdx.x, lane = tid & 31, wid = tid >> 5;
    int base = tid * 10;
    int v[10]; int s = 0;
    #pragma unroll
    for (int j = 0; j < 10; j++) {
        int i = base + j;
        v[j] = (i < NN) ? g_cnt[i] : 0;
        s += v[j];
    }
    int x = s;
    #pragma unroll
    for (int o = 1; o < 32; o <<= 1) {
        int y = __shfl_up_sync(0xffffffffu, x, o);
        if (lane >= o) x += y;
    }
    if (lane == 31) warp_sums[wid] = x;
    __syncthreads();
    if (wid == 0) {
        int t = warp_sums[lane];
        #pragma unroll
        for (int o = 1; o < 32; o <<= 1) {
            int y = __shfl_up_sync(0xffffffffu, t, o);
            if (lane >= o) t += y;
        }
        warp_sums[lane] = t;
    }
    __syncthreads();
    int prefix = ((wid > 0) ? warp_sums[wid - 1] : 0) + (x - s);
    #pragma unroll
    for (int j = 0; j < 10; j++) {
        int i = base + j;
        if (i < NN) { g_off[i] = prefix; g_pos[i] = prefix; }
        prefix += v[j];
    }
    if (tid == 1023) g_off[NN] = prefix;
}
__global__ void k_fill(const int* __restrict__ esrc, const int* __restrict__ edst,
                       const float* __restrict__ ew) {
    int i = blockIdx.x * blockDim.x + threadIdx.x;
    if (i < EE) {
        int d = edst[i];
        int p = atomicAdd(&g_pos[d], 1);
        g_csr_pair[p] = make_int2(esrc[i], __float_as_int(ew[i]));
    }
}

// ---------------- both biases at once (2 warps) ----------------
__global__ void k_bias2(const float* __restrict__ b1, const float* __restrict__ b2) {
    int lane = threadIdx.x & 31, w = threadIdx.x >> 5;   // w = layer
    const float* b = (w == 0) ? b1 : b2;
    const float4* bp = (const float4*)b;
    float4 v0 = bp[lane], v1 = bp[lane + 32];
    float n = rownorm(v0, v1);
    float s = tanh_acc(n) / n;
    v0 = s4(v0, s); v1 = s4(v1, s);
    float n2 = rownorm(v0, v1);
    if (n2 > MAXNORM) { float f = MAXNORM / n2; v0 = s4(v0, f); v1 = s4(v1, f); }
    float y2 = wredsum(d4(v0) + d4(v1));
    float4* gb = (float4*)(g_bias + w * 256);
    gb[lane] = v0; gb[lane + 32] = v1;
    if (lane == 0) g_biasy2v[w] = y2;
}

// ---------------- HMMA bf16-split GEMM + fused HypLinear/logmap0 ----------
// CTA tile 64 rows x 256 cols (full width), grid 158. 8 warps: wm=wid&1 (2),
// wn=wid>>1 (4); warp tile 32x64. Epilogue: row scalars via shfl+smem, then
// xt = A2*mx + B2*bias written directly as fp16.
__device__ __forceinline__ void ldsm4(uint32_t addr, uint32_t* r) {
    asm volatile("ldmatrix.sync.aligned.m8n8.x4.shared.b16 {%0,%1,%2,%3}, [%4];"
                 : "=r"(r[0]), "=r"(r[1]), "=r"(r[2]), "=r"(r[3]) : "r"(addr));
}
__device__ __forceinline__ void mma16816(float* c, const uint32_t* a, uint32_t b0, uint32_t b1) {
    asm volatile(
        "mma.sync.aligned.m16n8k16.row.col.f32.bf16.bf16.f32 "
        "{%0,%1,%2,%3}, {%4,%5,%6,%7}, {%8,%9}, {%0,%1,%2,%3};"
        : "+f"(c[0]), "+f"(c[1]), "+f"(c[2]), "+f"(c[3])
        : "r"(a[0]), "r"(a[1]), "r"(a[2]), "r"(a[3]), "r"(b0), "r"(b1));
}

#define HS_AH 0
#define HS_AL 8192
#define HS_BH 16384
#define HS_BL 49152
#define HS_TOTAL 81920

__global__ __launch_bounds__(256, 2) void k_hmma(int layer) {
    extern __shared__ __align__(1024) char smem[];
    uint32_t sb;
    asm("{ .reg .u64 t; cvta.to.shared.u64 t, %1; cvt.u32.u64 %0, t; }" : "=r"(sb) : "l"(smem));
    int tid = threadIdx.x, lane = tid & 31, wid = tid >> 5;
    int wm = wid & 1, wn = wid >> 1;
    int m0 = blockIdx.x * 64;
    const __nv_bfloat16* wh = g_wh + (size_t)layer * 65536;
    const __nv_bfloat16* wl = g_wl + (size_t)layer * 65536;

    float acc[2][8][4];
    #pragma unroll
    for (int mt = 0; mt < 2; mt++)
        #pragma unroll
        for (int nt = 0; nt < 8; nt++)
            #pragma unroll
            for (int q = 0; q < 4; q++) acc[mt][nt][q] = 0.f;

    for (int ch = 0; ch < 4; ch++) {
        int k0 = ch * 64;
        // A tiles: 64 rows x 64 bf16 = 512 uint4 each
        #pragma unroll
        for (int i = 0; i < 2; i++) {
            int idx = tid + 256 * i;            // 0..511
            int r = idx >> 3, c = idx & 7;
            uint32_t dst = (uint32_t)(r * 8 + (c ^ (r & 7))) * 16;
            *(uint4*)(smem + HS_AH + dst) = *(const uint4*)(g_ah + (size_t)(m0 + r) * 256 + k0 + c * 8);
            *(uint4*)(smem + HS_AL + dst) = *(const uint4*)(g_al + (size_t)(m0 + r) * 256 + k0 + c * 8);
        }
        // B tiles: 256 rows x 64 bf16 = 2048 uint4 each
        #pragma unroll
        for (int i = 0; i < 8; i++) {
            int idx = tid + 256 * i;            // 0..2047
            int r = idx >> 3, c = idx & 7;
            uint32_t dst = (uint32_t)(r * 8 + (c ^ (r & 7))) * 16;
            *(uint4*)(smem + HS_BH + dst) = *(const uint4*)(wh + (size_t)r * 256 + k0 + c * 8);
            *(uint4*)(smem + HS_BL + dst) = *(const uint4*)(wl + (size_t)r * 256 + k0 + c * 8);
        }
        __syncthreads();
        #pragma unroll
        for (int kk = 0; kk < 4; kk++) {
            uint32_t ah[2][4], al[2][4];
            #pragma unroll
            for (int mt = 0; mt < 2; mt++) {
                int row = wm * 32 + mt * 16 + (lane & 15);
                int ck = kk * 2 + (lane >> 4);
                uint32_t off = (uint32_t)(row * 8 + (ck ^ (row & 7))) * 16;
                ldsm4(sb + HS_AH + off, ah[mt]);
                ldsm4(sb + HS_AL + off, al[mt]);
            }
            #pragma unroll
            for (int ng = 0; ng < 4; ng++) {
                int row = wn * 64 + ng * 16 + ((lane >> 4) << 3) + (lane & 7);
                int ck = kk * 2 + ((lane >> 3) & 1);
                uint32_t off = (uint32_t)(row * 8 + (ck ^ (row & 7))) * 16;
                uint32_t bh[4], bl[4];
                ldsm4(sb + HS_BH + off, bh);
                ldsm4(sb + HS_BL + off, bl);
                #pragma unroll
                for (int mt = 0; mt < 2; mt++) {
                    mma16816(acc[mt][ng*2+0], ah[mt], bh[0], bh[1]);
                    mma16816(acc[mt][ng*2+0], ah[mt], bl[0], bl[1]);
                    mma16816(acc[mt][ng*2+0], al[mt], bh[0], bh[1]);
                    mma16816(acc[mt][ng*2+1], ah[mt], bh[2], bh[3]);
                    mma16816(acc[mt][ng*2+1], ah[mt], bl[2], bl[3]);
                    mma16816(acc[mt][ng*2+1], al[mt], bh[2], bh[3]);
                }
            }
        }
        __syncthreads();
    }

    // ---- fused epilogue (tiles dead; reuse smem) ----
    float* red  = (float*)smem;            // [64][4] mn2 partials
    float* redd = (float*)(smem + 1024);   // [64][4] dot partials
    float* bsm  = (float*)(smem + 2048);   // 256 bias floats
    if (tid < 64) ((float4*)bsm)[tid] = ((const float4*)(g_bias + layer * 256))[tid];
    __syncthreads();

    #pragma unroll
    for (int mt = 0; mt < 2; mt++) {
        #pragma unroll
        for (int half = 0; half < 2; half++) {
            float pm = 0.f, pd = 0.f;
            #pragma unroll
            for (int nt = 0; nt < 8; nt++) {
                float v0 = acc[mt][nt][half*2+0], v1 = acc[mt][nt][half*2+1];
                int col = wn * 64 + nt * 8 + 2 * (lane & 3);
                pm = fmaf(v0, v0, fmaf(v1, v1, pm));
                pd = fmaf(v0, bsm[col], fmaf(v1, bsm[col+1], pd));
            }
            pm += __shfl_xor_sync(0xffffffffu, pm, 1);
            pm += __shfl_xor_sync(0xffffffffu, pm, 2);
            pd += __shfl_xor_sync(0xffffffffu, pd, 1);
            pd += __shfl_xor_sync(0xffffffffu, pd, 2);
            int r = wm * 32 + mt * 16 + half * 8 + (lane >> 2);
            if ((lane & 3) == 0) { red[r*4 + wn] = pm; redd[r*4 + wn] = pd; }
        }
    }
    __syncthreads();

    float y2 = g_biasy2v[layer];
    float A2v[2][2], B2v[2][2];
    #pragma unroll
    for (int mt = 0; mt < 2; mt++) {
        #pragma unroll
        for (int half = 0; half < 2; half++) {
            int r = wm * 32 + mt * 16 + half * 8 + (lane >> 2);
            int grow = m0 + r;
            float mn2 = red[r*4] + red[r*4+1] + red[r*4+2] + red[r*4+3];
            float dot = redd[r*4] + redd[r*4+1] + redd[r*4+2] + redd[r*4+3];
            float xn = (grow < NN) ? g_xn[grow] : 0.5f;
            bool zero = (mn2 == 0.f);
            float mxn = fmaxf(sqrtf(mn2), MINNORM);
            float arg = mxn / xn * atanh_clip(xn);
            float sc = tanh_acc(arg) / mxn;
            if (zero) sc = 0.f;
            float rn = sc * mxn;
            float f1 = (rn > MAXNORM) ? MAXNORM / rn : 1.f;
            float s1 = sc * f1;
            float x2 = s1 * s1 * mn2;
            float xy = s1 * dot;
            float ca = 1.f + 2.f * xy + y2;
            float cb = 1.f - x2;
            float den = fmaxf(1.f + 2.f * xy + x2 * y2, MINNORM);
            float A1 = ca * s1 / den, B1 = cb / den;
            float qn2 = A1 * A1 * mn2 + 2.f * A1 * B1 * dot + B1 * B1 * y2;
            float qn = fmaxf(sqrtf(qn2), MINNORM);
            float f2 = (qn > MAXNORM) ? MAXNORM / qn : 1.f;
            float pn = fmaxf(qn * f2, MINNORM);
            float ls = atanh_clip(pn) / pn;
            A2v[mt][half] = ls * f2 * A1;
            B2v[mt][half] = ls * f2 * B1;
        }
    }

    #pragma unroll
    for (int mt = 0; mt < 2; mt++) {
        #pragma unroll
        for (int half = 0; half < 2; half++) {
            int r = wm * 32 + mt * 16 + half * 8 + (lane >> 2);
            int grow = m0 + r;
            if (grow >= NN) continue;
            float A2 = A2v[mt][half], B2 = B2v[mt][half];
            #pragma unroll
            for (int nt = 0; nt < 8; nt++) {
                int col = wn * 64 + nt * 8 + 2 * (lane & 3);
                float v0 = fmaf(A2, acc[mt][nt][half*2+0], B2 * bsm[col]);
                float v1 = fmaf(A2, acc[mt][nt][half*2+1], B2 * bsm[col+1]);
                __half2 h = __float22half2_rn(make_float2(v0, v1));
                *(__half2*)(g_xth + (size_t)grow * 256 + col) = h;
            }
        }
    }
}

// ---------------- fused CSR aggregation (fp16 gather) + HypAgg/HypAct ----
__global__ __launch_bounds__(256) void k_aggpost(float* __restrict__ out, int write_out) {
    int lane = threadIdx.x & 31;
    int row = blockIdx.x * 8 + (threadIdx.x >> 5);
    if (row >= NN) return;
    int beg = g_off[row], end = g_off[row + 1];

    float acc[8];
    #pragma unroll
    for (int j = 0; j < 8; j++) acc[j] = 0.f;

    for (int c = beg; c < end; c += 32) {
        int n = end - c; if (n > 32) n = 32;
        int2 pv = make_int2(0, 0);
        if (lane < n) pv = __ldg(&g_csr_pair[c + lane]);
        int j = 0;
        for (; j + 1 < n; j += 2) {
            int   s0 = __shfl_sync(0xffffffffu, pv.x, j);
            int   s1 = __shfl_sync(0xffffffffu, pv.x, j + 1);
            float w0 = __int_as_float(__shfl_sync(0xffffffffu, pv.y, j));
            float w1 = __int_as_float(__shfl_sync(0xffffffffu, pv.y, j + 1));
            uint4 u = __ldg((const uint4*)(g_xth + (size_t)s0 * 256) + lane);
            uint4 t = __ldg((const uint4*)(g_xth + (size_t)s1 * 256) + lane);
            const __half2* uh = (const __half2*)&u;
            const __half2* th = (const __half2*)&t;
            #pragma unroll
            for (int q = 0; q < 4; q++) {
                float2 fu = __half22float2(uh[q]);
                float2 ft = __half22float2(th[q]);
                acc[q*2+0] = fmaf(fu.x, w0, acc[q*2+0]);
                acc[q*2+1] = fmaf(fu.y, w0, acc[q*2+1]);
                acc[q*2+0] = fmaf(ft.x, w1, acc[q*2+0]);
                acc[q*2+1] = fmaf(ft.y, w1, acc[q*2+1]);
            }
        }
        if (j < n) {
            int   s0 = __shfl_sync(0xffffffffu, pv.x, j);
            float w0 = __int_as_float(__shfl_sync(0xffffffffu, pv.y, j));
            uint4 u = __ldg((const uint4*)(g_xth + (size_t)s0 * 256) + lane);
            const __half2* uh = (const __half2*)&u;
            #pragma unroll
            for (int q = 0; q < 4; q++) {
                float2 fu = __half22float2(uh[q]);
                acc[q*2+0] = fmaf(fu.x, w0, acc[q*2+0]);
                acc[q*2+1] = fmaf(fu.y, w0, acc[q*2+1]);
            }
        }
    }

    float4 a0 = make_float4(acc[0], acc[1], acc[2], acc[3]);
    float4 a1 = make_float4(acc[4], acc[5], acc[6], acc[7]);

    float n1 = rownorm(a0, a1);
    float s = tanh_acc(n1) / n1;
    float4 e0 = s4(a0, s), e1 = s4(a1, s);
    float n2 = rownorm(e0, e1);
    if (n2 > MAXNORM) { float f = MAXNORM / n2; e0 = s4(e0, f); e1 = s4(e1, f); }
    float pn = rownorm(e0, e1);
    float ls = atanh_clip(pn) / pn;
    float4 u0, u1;
    u0.x = fmaxf(e0.x * ls, 0.f); u0.y = fmaxf(e0.y * ls, 0.f);
    u0.z = fmaxf(e0.z * ls, 0.f); u0.w = fmaxf(e0.w * ls, 0.f);
    u1.x = fmaxf(e1.x * ls, 0.f); u1.y = fmaxf(e1.y * ls, 0.f);
    u1.z = fmaxf(e1.z * ls, 0.f); u1.w = fmaxf(e1.w * ls, 0.f);
    float un = rownorm(u0, u1);
    float s2 = tanh_acc(un) / un;
    float4 o0 = s4(u0, s2), o1 = s4(u1, s2);
    float n3 = rownorm(o0, o1);
    if (n3 > MAXNORM) { float f = MAXNORM / n3; o0 = s4(o0, f); o1 = s4(o1, f); }

    if (write_out) {
        float4* dst = (float4*)(out + (size_t)row * 256);
        dst[2*lane] = o0; dst[2*lane+1] = o1;
    } else {
        if (lane == 0) g_xn[row] = fminf(n3, MAXNORM);
        float f[8] = {o0.x, o0.y, o0.z, o0.w, o1.x, o1.y, o1.z, o1.w};
        write_split(row, lane, f);
    }
}

// ---------------- launch ----------------
extern "C" void kernel_launch(void* const* d_in, const int* in_sizes, int n_in,
                              void* d_out, int out_size) {
    const float* x    = (const float*)d_in[0];
    const float* W1   = (const float*)d_in[1];
    const float* b1   = (const float*)d_in[2];
    const float* W2   = (const float*)d_in[3];
    const float* b2   = (const float*)d_in[4];
    const float* ew   = (const float*)d_in[5];
    const int*   esrc = (const int*)d_in[6];
    const int*   edst = (const int*)d_in[7];
    float* out = (float*)d_out;
    (void)in_sizes; (void)n_in; (void)out_size;

    const int rowBlocks = (NN + 7) / 8;         // 1250 (== EE/256 exactly)
    const int eBlocks   = (EE + 255) / 256;

    cudaFuncSetAttribute(k_hmma, cudaFuncAttributeMaxDynamicSharedMemorySize, HS_TOTAL);

    k_convW<<<64, 256>>>(W1, W2);               // also zeroes g_cnt
    k_init<<<rowBlocks, 256>>>(x, edst);        // also does the edge histogram
    k_scan<<<1, 1024>>>();
    k_fill<<<eBlocks, 256>>>(esrc, edst, ew);
    k_bias2<<<1, 64>>>(b1, b2);

    // layer 1
    k_hmma<<<GBX, 256, HS_TOTAL>>>(0);
    k_aggpost<<<rowBlocks, 256>>>(out, 0);

    // layer 2
    k_hmma<<<GBX, 256, HS_TOTAL>>>(1);
    k_aggpost<<<rowBlocks, 256>>>(out, 1);
}